// round 3
// baseline (speedup 1.0000x reference)
#include <cuda_runtime.h>
#include <math.h>

#define BB   16
#define CIN  20
#define HH   256
#define WW   256
#define WD   64
#define M1   16
#define M2   16
#define NL   4
#define FCH  128
#define COUTC 20
#define NPIX 65536

typedef unsigned long long u64;

// ---------------- packed f32x2 helpers (Blackwell) ---------------------------
__device__ __forceinline__ u64 pk2(float lo, float hi) {
    u64 r; asm("mov.b64 %0, {%1, %2};" : "=l"(r) : "f"(lo), "f"(hi)); return r;
}
__device__ __forceinline__ u64 dup2(float v) { return pk2(v, v); }
__device__ __forceinline__ void upk2(u64 p, float& lo, float& hi) {
    asm("mov.b64 {%0, %1}, %2;" : "=f"(lo), "=f"(hi) : "l"(p));
}
__device__ __forceinline__ u64 fma2(u64 a, u64 b, u64 c) {
    u64 d; asm("fma.rn.f32x2 %0, %1, %2, %3;" : "=l"(d) : "l"(a), "l"(b), "l"(c)); return d;
}

// ---------------- scratch (device globals; no allocation allowed) -------------
__device__ float g_h  [BB*WD*NPIX];          // activations, in-place per layer (268 MB)
__device__ float g_Gx [BB*WD*HH*32];         // after x-DFT: [row=(bc*256+y)][32]
__device__ float g_Xft[BB*WD*512*2];         // [(b*64+c)*512 + mode] complex interleaved
__device__ float g_Tr [BB*WD*512];           // mixed modes, real plane
__device__ float g_Ti [BB*WD*512];           // mixed modes, imag plane
__device__ float g_G2 [BB*WD*HH*32];         // after inverse-y: [((b*64+o)*256+y)*32]
// basis tables
__device__ float g_bFx[WW*32];               // [x*32 + 2k(+1)]  e^{-i 2pi k x/256}
__device__ float g_bFy[HH*64];               // [y*64 + 2m(+1)]  e^{-i 2pi ky y/256}
__device__ float g_bIy[64*HH];               // TRANSPOSED [t*256+y], t=2m: cos, 2m+1: +sin
__device__ float g_bIx[32*WW];               // TRANSPOSED [t*256+x], t=2k: c*cos/65536, 2k+1: -c*sin/65536

__device__ __forceinline__ float gelu_f(float v) {
    return 0.5f * v * (1.0f + erff(v * 0.70710678118654752440f));
}

// ---------------- init basis --------------------------------------------------
__global__ void k_init_basis() {
    int t = blockIdx.x * blockDim.x + threadIdx.x;
    if (t < WW * M2) {
        int x = t >> 4, k = t & 15;
        double ang = (double)(k * x) / 128.0;   // theta / pi
        double s, c; sincospi(ang, &s, &c);
        g_bFx[x * 32 + 2 * k]     = (float)c;
        g_bFx[x * 32 + 2 * k + 1] = (float)(-s);
        double cc = (k == 0) ? 1.0 : 2.0;
        g_bIx[(2 * k) * WW + x]     = (float)( cc * c / 65536.0);
        g_bIx[(2 * k + 1) * WW + x] = (float)(-cc * s / 65536.0);
    }
    if (t < HH * 32) {
        int y = t >> 5, m = t & 31;
        int ky = (m < 16) ? m : (m + 224);
        double ang = (double)(ky * y) / 128.0;
        double s, c; sincospi(ang, &s, &c);
        g_bFy[y * 64 + 2 * m]     = (float)c;
        g_bFy[y * 64 + 2 * m + 1] = (float)(-s);
        g_bIy[(2 * m) * HH + y]     = (float)c;
        g_bIy[(2 * m + 1) * HH + y] = (float)s;
    }
}

// ---------------- lift: h = fc0(x), packed over output-channel pairs ----------
__global__ void __launch_bounds__(256) k_lift(const float* __restrict__ x,
                                              const float* __restrict__ w,
                                              const float* __restrict__ b) {
    __shared__ float wsT[CIN * WD];   // [c*64 + d]
    __shared__ float bs[WD];
    int tid = threadIdx.x;
    for (int l = tid; l < CIN * WD; l += 256) {
        int c = l >> 6, d = l & 63;
        wsT[l] = w[d * CIN + c];
    }
    if (tid < WD) bs[tid] = b[tid];
    __syncthreads();
    int pix = blockIdx.x * 256 + tid;
    int bb = pix >> 16;
    int p  = pix & 65535;
    u64 in2[CIN];
#pragma unroll
    for (int c = 0; c < CIN; c++) in2[c] = dup2(x[(bb * CIN + c) * NPIX + p]);
    float* orow = g_h + (bb * WD) * NPIX + p;
#pragma unroll 4
    for (int dp = 0; dp < 32; dp++) {
        u64 acc = pk2(bs[2 * dp], bs[2 * dp + 1]);
#pragma unroll
        for (int c = 0; c < CIN; c++)
            acc = fma2(in2[c], *(const u64*)(wsT + c * 64 + 2 * dp), acc);
        float lo, hi; upk2(acc, lo, hi);
        orow[(2 * dp) * NPIX]     = lo;
        orow[(2 * dp + 1) * NPIX] = hi;
    }
}

// ---------------- forward DFT along x: Gx[R,32] = h[R,256] * Bx[256,32] -------
__global__ void __launch_bounds__(256) k_fwdX() {
    __shared__ float As[256 * 33];
    __shared__ float Bs[32 * 34];     // stride 34 -> 8B-aligned pairs
    int rowbase = blockIdx.x * 256;
    int tid = threadIdx.x;
    int ri = tid >> 3;   // 0..31  (rows ri + 32j)
    int ci = tid & 7;    // 0..7   (cols ci*4 .. ci*4+3)
    u64 acc[8][2];
#pragma unroll
    for (int j = 0; j < 8; j++) { acc[j][0] = 0ULL; acc[j][1] = 0ULL; }
    for (int xc = 0; xc < 8; xc++) {
        if (xc) __syncthreads();
        for (int l = tid; l < 8192; l += 256) {
            int rr = l >> 5, xx = l & 31;
            As[rr * 33 + xx] = g_h[(rowbase + rr) * 256 + xc * 32 + xx];
        }
        for (int l = tid; l < 1024; l += 256) {
            int xx = l >> 5, t = l & 31;
            Bs[xx * 34 + t] = g_bFx[(xc * 32 + xx) * 32 + t];
        }
        __syncthreads();
#pragma unroll 4
        for (int xx = 0; xx < 32; xx++) {
            u64 b01 = *(const u64*)(Bs + xx * 34 + ci * 4);
            u64 b23 = *(const u64*)(Bs + xx * 34 + ci * 4 + 2);
#pragma unroll
            for (int j = 0; j < 8; j++) {
                u64 a2 = dup2(As[(ri + 32 * j) * 33 + xx]);
                acc[j][0] = fma2(a2, b01, acc[j][0]);
                acc[j][1] = fma2(a2, b23, acc[j][1]);
            }
        }
    }
#pragma unroll
    for (int j = 0; j < 8; j++) {
        int row = rowbase + ri + 32 * j;
        float a0, a1, a2v, a3;
        upk2(acc[j][0], a0, a1);
        upk2(acc[j][1], a2v, a3);
        *(float4*)(g_Gx + row * 32 + ci * 4) = make_float4(a0, a1, a2v, a3);
    }
}

// ---------------- forward DFT along y (256 -> 32 modes), complex --------------
__global__ void __launch_bounds__(512) k_fwdY() {
    __shared__ float s[HH * 32];   // 32 KB
    int bc = blockIdx.x;
    const float* src = g_Gx + bc * HH * 32;
    for (int l = threadIdx.x; l < HH * 32; l += 512) s[l] = src[l];
    __syncthreads();
    int t = threadIdx.x;          // mode = m*16 + k
    int m = t >> 4, k = t & 15;
    float re[4] = {0, 0, 0, 0}, im[4] = {0, 0, 0, 0};
    const float* wb = g_bFy + 2 * m;
    for (int y = 0; y < HH; y += 4) {
#pragma unroll
        for (int q = 0; q < 4; q++) {
            float2 g = *(const float2*)(s + (y + q) * 32 + 2 * k);
            float2 w = *(const float2*)(wb + (y + q) * 64);
            re[q] += g.x * w.x - g.y * w.y;
            im[q] += g.x * w.y + g.y * w.x;
        }
    }
    float rr = (re[0] + re[1]) + (re[2] + re[3]);
    float ii = (im[0] + im[1]) + (im[2] + im[3]);
    *(float2*)(g_Xft + (bc * 512 + t) * 2) = make_float2(rr, ii);
}

// ---------------- channel mix per mode: T[b,o] = sum_i X[b,i] * W[i,o] --------
__global__ void __launch_bounds__(256) k_mix(const float* __restrict__ w1r,
                                             const float* __restrict__ w1i,
                                             const float* __restrict__ w2r,
                                             const float* __restrict__ w2i,
                                             int layer) {
    __shared__ float Ws[WD * WD * 2];   // 32 KB, [ (i*64+o)*2 ]
    __shared__ float Xs[BB * WD * 2];   // 8 KB,  [ (b*64+i)*2 ]
    int mode = blockIdx.x;              // 0..511
    int m = mode >> 4;
    const float* wr; const float* wi; int off;
    if (m < 16) { wr = w1r; wi = w1i; off = mode; }
    else        { wr = w2r; wi = w2i; off = mode - 256; }
    int lbase = layer * WD * WD * 256;
    for (int l = threadIdx.x; l < WD * WD; l += 256) {
        Ws[l * 2]     = wr[lbase + l * 256 + off];
        Ws[l * 2 + 1] = wi[lbase + l * 256 + off];
    }
    for (int l = threadIdx.x; l < BB * WD; l += 256) {
        float2 v = *(const float2*)(g_Xft + (l * 512 + mode) * 2);
        *(float2*)(Xs + l * 2) = v;
    }
    __syncthreads();
    int o  = threadIdx.x & 63;
    int bq = threadIdx.x >> 6;    // 0..3 -> b = bq*4 + q
    u64 acc[4] = {0ULL, 0ULL, 0ULL, 0ULL};   // packed (re, im)
    for (int i = 0; i < WD; i++) {
        float2 w = *(const float2*)(Ws + (i * 64 + o) * 2);
        u64 wA = pk2(w.x, w.y);
        u64 wB = pk2(-w.y, w.x);
#pragma unroll
        for (int q = 0; q < 4; q++) {
            float2 xv = *(const float2*)(Xs + ((bq * 4 + q) * 64 + i) * 2);
            acc[q] = fma2(dup2(xv.x), wA, acc[q]);
            acc[q] = fma2(dup2(xv.y), wB, acc[q]);
        }
    }
#pragma unroll
    for (int q = 0; q < 4; q++) {
        int b = bq * 4 + q;
        float ar, ai; upk2(acc[q], ar, ai);
        g_Tr[(b * 64 + o) * 512 + mode] = ar;
        g_Ti[(b * 64 + o) * 512 + mode] = ai;
    }
}

// ---------------- inverse DFT along y (32 modes -> 256), complex --------------
__global__ void __launch_bounds__(256) k_invY() {
    __shared__ float TsR[512];
    __shared__ float TsI[512];
    __shared__ float smt[256 * 33];
    int bo = blockIdx.x;
    for (int l = threadIdx.x; l < 512; l += 256) {
        TsR[l] = g_Tr[bo * 512 + l];
        TsI[l] = g_Ti[bo * 512 + l];
    }
    __syncthreads();
    int y = threadIdx.x;
    u64 aR[8], aI[8];
#pragma unroll
    for (int i = 0; i < 8; i++) { aR[i] = 0ULL; aI[i] = 0ULL; }
#pragma unroll 2
    for (int m = 0; m < 32; m++) {
        float cr = g_bIy[(2 * m) * HH + y];
        float ci = g_bIy[(2 * m + 1) * HH + y];
        u64 crr = dup2(cr), cii = dup2(ci), nci = dup2(-ci);
#pragma unroll
        for (int kp = 0; kp < 8; kp++) {
            u64 tr2 = *(const u64*)(TsR + m * 16 + 2 * kp);
            u64 ti2 = *(const u64*)(TsI + m * 16 + 2 * kp);
            aR[kp] = fma2(tr2, crr, aR[kp]);
            aR[kp] = fma2(ti2, nci, aR[kp]);
            aI[kp] = fma2(tr2, cii, aI[kp]);
            aI[kp] = fma2(ti2, crr, aI[kp]);
        }
    }
#pragma unroll
    for (int kp = 0; kp < 8; kp++) {
        float r0, r1, i0, i1;
        upk2(aR[kp], r0, r1);
        upk2(aI[kp], i0, i1);
        smt[y * 33 + 4 * kp]     = r0;
        smt[y * 33 + 4 * kp + 1] = i0;
        smt[y * 33 + 4 * kp + 2] = r1;
        smt[y * 33 + 4 * kp + 3] = i1;
    }
    __syncthreads();
    float* dst = g_G2 + bo * 8192;
    for (int l = threadIdx.x; l < 8192; l += 256)
        dst[l] = smt[(l >> 5) * 33 + (l & 31)];
}

// ---------------- fused: inverse-x + 1x1 conv + bias (+GELU), in place -------
#define FUSE_SMEM ((16384 + 4096 + 2048 + 64) * 4)
__global__ void __launch_bounds__(256) k_fuse(const float* __restrict__ pw_w,
                                              const float* __restrict__ pw_b,
                                              int layer, int apply_gelu) {
    extern __shared__ float sm[];
    float* in_s = sm;               // 64*256
    float* w_s  = sm + 16384;       // 64*64  [i*64+o]
    float* g2_s = w_s + 4096;       // 64*32  [o*32+t]
    float* b_s  = g2_s + 2048;      // 64
    int bb = blockIdx.x >> 8;
    int y  = blockIdx.x & 255;
    int tid = threadIdx.x;
    const float* hrow = g_h + (bb * WD) * NPIX + y * 256;
    for (int l = tid; l < 16384; l += 256) {
        int i = l >> 8, x = l & 255;
        in_s[l] = hrow[i * NPIX + x];
    }
    for (int l = tid; l < 4096; l += 256) {
        int i = l >> 6, o = l & 63;
        w_s[l] = pw_w[(layer * WD + o) * WD + i];
    }
    if (tid < WD) b_s[tid] = pw_b[layer * WD + tid];
    {
        const float* g2row = g_G2 + (bb * WD) * 8192 + y * 32;
        for (int l = tid; l < 2048; l += 256) {
            int o = l >> 5, t = l & 31;
            g2_s[l] = g2row[o * 8192 + t];
        }
    }
    __syncthreads();
    int lane = tid & 31;
    int to   = tid >> 5;           // o-group 0..7, constant within warp
    int x0   = lane * 8;
    u64 acc[8][4];
#pragma unroll
    for (int v = 0; v < 8; v++) {
        u64 bv = dup2(b_s[to * 8 + v]);
#pragma unroll
        for (int u = 0; u < 4; u++) acc[v][u] = bv;
    }
    // pointwise conv: acc[v][:] += h[i][:] * w[i][v]
    for (int i = 0; i < 64; i++) {
        ulonglong2 ha = *(const ulonglong2*)(in_s + i * 256 + x0);
        ulonglong2 hb = *(const ulonglong2*)(in_s + i * 256 + x0 + 4);
        float4 wa = *(const float4*)(w_s + i * 64 + to * 8);
        float4 wb = *(const float4*)(w_s + i * 64 + to * 8 + 4);
        u64 wd[8] = {dup2(wa.x), dup2(wa.y), dup2(wa.z), dup2(wa.w),
                     dup2(wb.x), dup2(wb.y), dup2(wb.z), dup2(wb.w)};
#pragma unroll
        for (int v = 0; v < 8; v++) {
            acc[v][0] = fma2(ha.x, wd[v], acc[v][0]);
            acc[v][1] = fma2(ha.y, wd[v], acc[v][1]);
            acc[v][2] = fma2(hb.x, wd[v], acc[v][2]);
            acc[v][3] = fma2(hb.y, wd[v], acc[v][3]);
        }
    }
    // spectral inverse-x: acc[v][:] += g2[v][t] * bIx[t][:]
    for (int t = 0; t < 32; t++) {
        ulonglong2 ca = *(const ulonglong2*)(g_bIx + t * 256 + x0);
        ulonglong2 cb = *(const ulonglong2*)(g_bIx + t * 256 + x0 + 4);
#pragma unroll
        for (int v = 0; v < 8; v++) {
            u64 gv = dup2(g2_s[(to * 8 + v) * 32 + t]);
            acc[v][0] = fma2(ca.x, gv, acc[v][0]);
            acc[v][1] = fma2(ca.y, gv, acc[v][1]);
            acc[v][2] = fma2(cb.x, gv, acc[v][2]);
            acc[v][3] = fma2(cb.y, gv, acc[v][3]);
        }
    }
    float* orow = g_h + (bb * WD) * NPIX + y * 256;
#pragma unroll
    for (int v = 0; v < 8; v++) {
        float r[8];
        upk2(acc[v][0], r[0], r[1]);
        upk2(acc[v][1], r[2], r[3]);
        upk2(acc[v][2], r[4], r[5]);
        upk2(acc[v][3], r[6], r[7]);
        if (apply_gelu) {
#pragma unroll
            for (int u = 0; u < 8; u++) r[u] = gelu_f(r[u]);
        }
        int o = to * 8 + v;
        *(float4*)(orow + o * NPIX + x0)     = make_float4(r[0], r[1], r[2], r[3]);
        *(float4*)(orow + o * NPIX + x0 + 4) = make_float4(r[4], r[5], r[6], r[7]);
    }
}

// ---------------- head: fc1(64->128)+GELU, fc2(128->20), fused ----------------
#define HEAD_SMEM ((16384 + 8192 + 8192 + 2560 + 128 + 32) * 4)
__global__ void __launch_bounds__(256) k_head(const float* __restrict__ w1,
                                              const float* __restrict__ b1,
                                              const float* __restrict__ w2,
                                              const float* __restrict__ b2,
                                              float* __restrict__ out) {
    extern __shared__ float sm[];
    float* h_s   = sm;                 // 64*256
    float* w1_s  = sm + 16384;         // 128*64  [d*64+i]
    float* hid_s = w1_s + 8192;        // 32*256 chunk
    float* w2t   = hid_s + 8192;       // 128*20  [d*20+e]
    float* b1_s  = w2t + 2560;         // 128
    float* b2_s  = b1_s + 128;         // 20
    int bb = blockIdx.x >> 8;
    int y  = blockIdx.x & 255;
    int tid = threadIdx.x;
    for (int l = tid; l < 16384; l += 256) {
        int i = l >> 8, x = l & 255;
        h_s[l] = g_h[(bb * WD + i) * NPIX + y * 256 + x];
    }
    for (int l = tid; l < 8192; l += 256) w1_s[l] = w1[l];
    for (int l = tid; l < 2560; l += 256) {
        int d = l / 20, e = l % 20;
        w2t[l] = w2[e * FCH + d];
    }
    if (tid < 128) b1_s[tid] = b1[tid];
    if (tid < 20)  b2_s[tid] = b2[tid];
    __syncthreads();
    u64 acc2[10];
#pragma unroll
    for (int e = 0; e < 10; e++) acc2[e] = 0ULL;
    int tx = tid & 31, td = tid >> 5, x0 = tx * 8;
    for (int chunk = 0; chunk < 4; chunk++) {
        u64 a[4][4];
#pragma unroll
        for (int v = 0; v < 4; v++) {
            u64 bv = dup2(b1_s[chunk * 32 + td * 4 + v]);
#pragma unroll
            for (int u = 0; u < 4; u++) a[v][u] = bv;
        }
        for (int i = 0; i < 64; i++) {
            ulonglong2 ha = *(const ulonglong2*)(h_s + i * 256 + x0);
            ulonglong2 hb = *(const ulonglong2*)(h_s + i * 256 + x0 + 4);
#pragma unroll
            for (int v = 0; v < 4; v++) {
                u64 wv = dup2(w1_s[(chunk * 32 + td * 4 + v) * 64 + i]);
                a[v][0] = fma2(ha.x, wv, a[v][0]);
                a[v][1] = fma2(ha.y, wv, a[v][1]);
                a[v][2] = fma2(hb.x, wv, a[v][2]);
                a[v][3] = fma2(hb.y, wv, a[v][3]);
            }
        }
#pragma unroll
        for (int v = 0; v < 4; v++) {
            float r[8];
            upk2(a[v][0], r[0], r[1]);
            upk2(a[v][1], r[2], r[3]);
            upk2(a[v][2], r[4], r[5]);
            upk2(a[v][3], r[6], r[7]);
#pragma unroll
            for (int u = 0; u < 8; u++) r[u] = gelu_f(r[u]);
            *(float4*)(hid_s + (td * 4 + v) * 256 + x0)     = make_float4(r[0], r[1], r[2], r[3]);
            *(float4*)(hid_s + (td * 4 + v) * 256 + x0 + 4) = make_float4(r[4], r[5], r[6], r[7]);
        }
        __syncthreads();
        for (int c = 0; c < 32; c++) {
            u64 h2 = dup2(hid_s[c * 256 + tid]);
            const u64* wp = (const u64*)(w2t + (chunk * 32 + c) * 20);
#pragma unroll
            for (int e = 0; e < 10; e++) acc2[e] = fma2(h2, wp[e], acc2[e]);
        }
        __syncthreads();
    }
    float* orow = out + (bb * COUTC) * NPIX + y * 256 + tid;
#pragma unroll
    for (int e = 0; e < 10; e++) {
        float lo, hi; upk2(acc2[e], lo, hi);
        orow[(2 * e) * NPIX]     = lo + b2_s[2 * e];
        orow[(2 * e + 1) * NPIX] = hi + b2_s[2 * e + 1];
    }
}

// ---------------- launch ------------------------------------------------------
extern "C" void kernel_launch(void* const* d_in, const int* in_sizes, int n_in,
                              void* d_out, int out_size) {
    const float* x    = (const float*)d_in[0];
    const float* w1r  = (const float*)d_in[1];
    const float* w1i  = (const float*)d_in[2];
    const float* w2r  = (const float*)d_in[3];
    const float* w2i  = (const float*)d_in[4];
    const float* pw_w = (const float*)d_in[5];
    const float* pw_b = (const float*)d_in[6];
    const float* fc0w = (const float*)d_in[7];
    const float* fc0b = (const float*)d_in[8];
    const float* fc1w = (const float*)d_in[9];
    const float* fc1b = (const float*)d_in[10];
    const float* fc2w = (const float*)d_in[11];
    const float* fc2b = (const float*)d_in[12];
    float* out = (float*)d_out;

    cudaFuncSetAttribute(k_fuse, cudaFuncAttributeMaxDynamicSharedMemorySize, FUSE_SMEM);
    cudaFuncSetAttribute(k_head, cudaFuncAttributeMaxDynamicSharedMemorySize, HEAD_SMEM);

    k_init_basis<<<32, 256>>>();
    k_lift<<<4096, 256>>>(x, fc0w, fc0b);
    for (int l = 0; l < NL; l++) {
        k_fwdX<<<1024, 256>>>();
        k_fwdY<<<1024, 512>>>();
        k_mix<<<512, 256>>>(w1r, w1i, w2r, w2i, l);
        k_invY<<<1024, 256>>>();
        k_fuse<<<4096, 256, FUSE_SMEM>>>(pw_w, pw_b, l, (l < NL - 1) ? 1 : 0);
    }
    k_head<<<4096, 256, HEAD_SMEM>>>(fc1w, fc1b, fc2w, fc2b, out);
}

// round 4
// speedup vs baseline: 1.0708x; 1.0708x over previous
#include <cuda_runtime.h>
#include <math.h>

#define BB   16
#define CIN  20
#define HH   256
#define WW   256
#define WD   64
#define M1   16
#define M2   16
#define NL   4
#define FCH  128
#define COUTC 20
#define NPIX 65536

// ---------------- scratch (device globals; no allocation allowed) -------------
__device__ float g_h  [BB*WD*NPIX];          // activations, in-place per layer (268 MB)
__device__ float g_Gx [BB*WD*HH*32];         // after x-DFT: [((b*64+c)*256+y)*32]
__device__ float g_Xft[BB*WD*512*2];         // [(b*64+c)*512 + mode] complex interleaved
__device__ float g_T  [BB*WD*512*2];         // mixed modes
__device__ float g_G2 [BB*WD*HH*32];         // after inverse-y: [((b*64+o)*256+y)*32]
// basis tables
__device__ float g_bFx[WW*32];               // [x*32 + 2k(+1)]  e^{-i 2pi k x/256}
__device__ float g_bFy[HH*64];               // [y*64 + 2m(+1)]  e^{-i 2pi ky y/256}
__device__ float g_bIy[64*HH];               // TRANSPOSED [t*256+y], t=2m: cos, 2m+1: +sin
__device__ float g_bIx[32*WW];               // TRANSPOSED [t*256+x], t=2k: c*cos/65536, 2k+1: -c*sin/65536

__device__ __forceinline__ float gelu_f(float v) {
    return 0.5f * v * (1.0f + erff(v * 0.70710678118654752440f));
}

// ---------------- init basis --------------------------------------------------
__global__ void k_init_basis() {
    int t = blockIdx.x * blockDim.x + threadIdx.x;
    if (t < WW * M2) {
        int x = t >> 4, k = t & 15;
        double ang = (double)(k * x) / 128.0;   // theta / pi
        double s, c; sincospi(ang, &s, &c);
        g_bFx[x * 32 + 2 * k]     = (float)c;
        g_bFx[x * 32 + 2 * k + 1] = (float)(-s);
        double cc = (k == 0) ? 1.0 : 2.0;
        g_bIx[(2 * k) * WW + x]     = (float)( cc * c / 65536.0);
        g_bIx[(2 * k + 1) * WW + x] = (float)(-cc * s / 65536.0);
    }
    if (t < HH * 32) {
        int y = t >> 5, m = t & 31;
        int ky = (m < 16) ? m : (m + 224);
        double ang = (double)(ky * y) / 128.0;
        double s, c; sincospi(ang, &s, &c);
        g_bFy[y * 64 + 2 * m]     = (float)c;
        g_bFy[y * 64 + 2 * m + 1] = (float)(-s);
        g_bIy[(2 * m) * HH + y]     = (float)c;
        g_bIy[(2 * m + 1) * HH + y] = (float)s;
    }
}

// ---------------- lift: h = fc0(x) -------------------------------------------
__global__ void __launch_bounds__(256) k_lift(const float* __restrict__ x,
                                              const float* __restrict__ w,
                                              const float* __restrict__ b) {
    __shared__ float ws[WD * CIN];
    __shared__ float bs[WD];
    int tid = threadIdx.x;
    for (int i = tid; i < WD * CIN; i += 256) ws[i] = w[i];
    if (tid < WD) bs[tid] = b[tid];
    __syncthreads();
    int pix = blockIdx.x * 256 + tid;
    int bb = pix >> 16;
    int p  = pix & 65535;
    float in[CIN];
#pragma unroll
    for (int c = 0; c < CIN; c++) in[c] = x[(bb * CIN + c) * NPIX + p];
#pragma unroll 4
    for (int d = 0; d < WD; d++) {
        float acc = bs[d];
#pragma unroll
        for (int c = 0; c < CIN; c++) acc += in[c] * ws[d * CIN + c];
        g_h[(bb * WD + d) * NPIX + p] = acc;
    }
}

// ---------------- forward DFT along x (standalone; used for layer 0 only) ----
__global__ void __launch_bounds__(256) k_fwdX() {
    __shared__ float As[256 * 33];
    __shared__ float Bs[32 * 33];
    int rowbase = blockIdx.x * 256;
    int tid = threadIdx.x;
    int ri = tid >> 3;   // 0..31  (rows ri + 32j)
    int ci = tid & 7;    // 0..7   (cols ci*4 .. ci*4+3)
    float acc[8][4];
#pragma unroll
    for (int j = 0; j < 8; j++)
#pragma unroll
        for (int c = 0; c < 4; c++) acc[j][c] = 0.f;
    for (int xc = 0; xc < 8; xc++) {
        if (xc) __syncthreads();
        for (int l = tid; l < 8192; l += 256) {
            int rr = l >> 5, xx = l & 31;
            As[rr * 33 + xx] = g_h[(rowbase + rr) * 256 + xc * 32 + xx];
        }
        for (int l = tid; l < 1024; l += 256) {
            int xx = l >> 5, t = l & 31;
            Bs[xx * 33 + t] = g_bFx[(xc * 32 + xx) * 32 + t];
        }
        __syncthreads();
#pragma unroll 4
        for (int xx = 0; xx < 32; xx++) {
            float b0 = Bs[xx * 33 + ci * 4 + 0];
            float b1 = Bs[xx * 33 + ci * 4 + 1];
            float b2 = Bs[xx * 33 + ci * 4 + 2];
            float b3 = Bs[xx * 33 + ci * 4 + 3];
#pragma unroll
            for (int j = 0; j < 8; j++) {
                float a = As[(ri + 32 * j) * 33 + xx];
                acc[j][0] += a * b0; acc[j][1] += a * b1;
                acc[j][2] += a * b2; acc[j][3] += a * b3;
            }
        }
    }
#pragma unroll
    for (int j = 0; j < 8; j++) {
        int row = rowbase + ri + 32 * j;
        *(float4*)(g_Gx + row * 32 + ci * 4) =
            make_float4(acc[j][0], acc[j][1], acc[j][2], acc[j][3]);
    }
}

// ---------------- forward DFT along y (256 -> 32 modes), complex --------------
// block = 128 threads, one (b,c) plane per block; thread owns 4 complex modes
__global__ void __launch_bounds__(128) k_fwdY() {
    __shared__ float s[HH * 32];   // 32 KB
    int bc = blockIdx.x;
    const float* src = g_Gx + bc * HH * 32;
    for (int l = threadIdx.x; l < HH * 32; l += 128) s[l] = src[l];
    __syncthreads();
    int m  = threadIdx.x >> 2;   // 0..31
    int kg = threadIdx.x & 3;    // 0..3 -> k = kg*4 .. kg*4+3
    float re[4] = {0, 0, 0, 0}, im[4] = {0, 0, 0, 0};
    const float* wp = g_bFy + 2 * m;
#pragma unroll 4
    for (int y = 0; y < HH; y++) {
        float4 ga = *(const float4*)(s + y * 32 + kg * 8);
        float4 gb = *(const float4*)(s + y * 32 + kg * 8 + 4);
        float2 w  = __ldg((const float2*)(wp + y * 64));
        re[0] += ga.x * w.x - ga.y * w.y;  im[0] += ga.x * w.y + ga.y * w.x;
        re[1] += ga.z * w.x - ga.w * w.y;  im[1] += ga.z * w.y + ga.w * w.x;
        re[2] += gb.x * w.x - gb.y * w.y;  im[2] += gb.x * w.y + gb.y * w.x;
        re[3] += gb.z * w.x - gb.w * w.y;  im[3] += gb.z * w.y + gb.w * w.x;
    }
    float* dst = g_Xft + (bc * 512 + m * 16 + kg * 4) * 2;
    *(float4*)(dst)     = make_float4(re[0], im[0], re[1], im[1]);
    *(float4*)(dst + 4) = make_float4(re[2], im[2], re[3], im[3]);
}

// ---------------- channel mix per mode: T[b,o] = sum_i X[b,i] * W[i,o] --------
__global__ void __launch_bounds__(256) k_mix(const float* __restrict__ w1r,
                                             const float* __restrict__ w1i,
                                             const float* __restrict__ w2r,
                                             const float* __restrict__ w2i,
                                             int layer) {
    __shared__ float Ws[WD * WD * 2];   // 32 KB, [ (i*64+o)*2 ]
    __shared__ float Xs[BB * WD * 2];   // 8 KB,  [ (b*64+i)*2 ]
    int mode = blockIdx.x;              // 0..511
    int m = mode >> 4;
    const float* wr; const float* wi; int off;
    if (m < 16) { wr = w1r; wi = w1i; off = mode; }
    else        { wr = w2r; wi = w2i; off = mode - 256; }
    int lbase = layer * WD * WD * 256;
    for (int l = threadIdx.x; l < WD * WD; l += 256) {
        Ws[l * 2]     = wr[lbase + l * 256 + off];
        Ws[l * 2 + 1] = wi[lbase + l * 256 + off];
    }
    for (int l = threadIdx.x; l < BB * WD; l += 256) {
        float2 v = *(const float2*)(g_Xft + (l * 512 + mode) * 2);
        *(float2*)(Xs + l * 2) = v;
    }
    __syncthreads();
    int o  = threadIdx.x & 63;
    int bq = threadIdx.x >> 6;    // 0..3 -> b = bq*4 + q
    float ar[4] = {0, 0, 0, 0}, ai[4] = {0, 0, 0, 0};
    for (int i = 0; i < WD; i++) {
        float2 w = *(const float2*)(Ws + (i * 64 + o) * 2);
#pragma unroll
        for (int q = 0; q < 4; q++) {
            float2 xv = *(const float2*)(Xs + ((bq * 4 + q) * 64 + i) * 2);
            ar[q] += xv.x * w.x - xv.y * w.y;
            ai[q] += xv.x * w.y + xv.y * w.x;
        }
    }
#pragma unroll
    for (int q = 0; q < 4; q++) {
        int b = bq * 4 + q;
        *(float2*)(g_T + ((b * 64 + o) * 512 + mode) * 2) = make_float2(ar[q], ai[q]);
    }
}

// ---------------- inverse DFT along y (32 modes -> 256), complex --------------
__global__ void __launch_bounds__(256) k_invY() {
    __shared__ float Ts[1024];
    __shared__ float smt[256 * 33];
    int bo = blockIdx.x;
    for (int l = threadIdx.x; l < 1024; l += 256) Ts[l] = g_T[bo * 1024 + l];
    __syncthreads();
    int y = threadIdx.x;
    float acc[32];
#pragma unroll
    for (int i = 0; i < 32; i++) acc[i] = 0.f;
#pragma unroll 2
    for (int m = 0; m < 32; m++) {
        float cr = g_bIy[(2 * m) * HH + y];
        float ci = g_bIy[(2 * m + 1) * HH + y];
#pragma unroll
        for (int k = 0; k < 16; k++) {
            float tr = Ts[(m * 16 + k) * 2], ti = Ts[(m * 16 + k) * 2 + 1];
            acc[2 * k]     += tr * cr - ti * ci;
            acc[2 * k + 1] += tr * ci + ti * cr;
        }
    }
#pragma unroll
    for (int u = 0; u < 32; u++) smt[y * 33 + u] = acc[u];
    __syncthreads();
    float* dst = g_G2 + bo * 8192;
    for (int l = threadIdx.x; l < 8192; l += 256)
        dst[l] = smt[(l >> 5) * 33 + (l & 31)];
}

// ---------------- fused: inverse-x + 1x1 conv + bias (+GELU +fwdX), in place --
#define FUSE_SMEM ((16384 + 4096 + 2048 + 64) * 4)
__global__ void __launch_bounds__(256) k_fuse(const float* __restrict__ pw_w,
                                              const float* __restrict__ pw_b,
                                              int layer, int gelu_and_gx) {
    extern __shared__ float sm[];
    float* in_s = sm;               // 64*256
    float* w_s  = sm + 16384;       // 64*64  [i*64+o]
    float* g2_s = w_s + 4096;       // 64*32  [o*32+t]
    float* b_s  = g2_s + 2048;      // 64
    int bb = blockIdx.x >> 8;
    int y  = blockIdx.x & 255;
    int tid = threadIdx.x;
    const float* hrow = g_h + (bb * WD) * NPIX + y * 256;
    for (int l = tid; l < 16384; l += 256) {
        int i = l >> 8, x = l & 255;
        in_s[l] = hrow[i * NPIX + x];
    }
    for (int l = tid; l < 4096; l += 256) {
        int i = l >> 6, o = l & 63;
        w_s[l] = pw_w[(layer * WD + o) * WD + i];
    }
    if (tid < WD) b_s[tid] = pw_b[layer * WD + tid];
    {
        const float* g2row = g_G2 + (bb * WD) * 8192 + y * 32;
        for (int l = tid; l < 2048; l += 256) {
            int o = l >> 5, t = l & 31;
            g2_s[l] = g2row[o * 8192 + t];
        }
    }
    __syncthreads();
    int lane = tid & 31;
    int to   = tid >> 5;           // o-group 0..7, constant within warp
    int x0   = lane * 8;
    float acc[8][8];
#pragma unroll
    for (int v = 0; v < 8; v++) {
        float bv = b_s[to * 8 + v];
#pragma unroll
        for (int u = 0; u < 8; u++) acc[v][u] = bv;
    }
    // pointwise conv
    for (int i = 0; i < 64; i++) {
        float4 h0 = *(const float4*)(in_s + i * 256 + x0);
        float4 h1 = *(const float4*)(in_s + i * 256 + x0 + 4);
        float4 w0 = *(const float4*)(w_s + i * 64 + to * 8);
        float4 w1 = *(const float4*)(w_s + i * 64 + to * 8 + 4);
        float hv[8] = {h0.x, h0.y, h0.z, h0.w, h1.x, h1.y, h1.z, h1.w};
        float wv[8] = {w0.x, w0.y, w0.z, w0.w, w1.x, w1.y, w1.z, w1.w};
#pragma unroll
        for (int v = 0; v < 8; v++)
#pragma unroll
            for (int u = 0; u < 8; u++) acc[v][u] += hv[u] * wv[v];
    }
    // spectral inverse-x
    for (int t = 0; t < 32; t++) {
        float4 c0 = __ldg((const float4*)(g_bIx + t * 256 + x0));
        float4 c1 = __ldg((const float4*)(g_bIx + t * 256 + x0 + 4));
        float cv[8] = {c0.x, c0.y, c0.z, c0.w, c1.x, c1.y, c1.z, c1.w};
        float gv[8];
#pragma unroll
        for (int v = 0; v < 8; v++) gv[v] = g2_s[(to * 8 + v) * 32 + t];
#pragma unroll
        for (int v = 0; v < 8; v++)
#pragma unroll
            for (int u = 0; u < 8; u++) acc[v][u] += gv[v] * cv[u];
    }
    float* orow = g_h + (bb * WD) * NPIX + y * 256;
    if (!gelu_and_gx) {
        // last layer: plain store, no GELU, no fwdX
#pragma unroll
        for (int v = 0; v < 8; v++) {
            int o = to * 8 + v;
            *(float4*)(orow + o * NPIX + x0) =
                make_float4(acc[v][0], acc[v][1], acc[v][2], acc[v][3]);
            *(float4*)(orow + o * NPIX + x0 + 4) =
                make_float4(acc[v][4], acc[v][5], acc[v][6], acc[v][7]);
        }
        return;
    }
    // GELU, store to gmem, and stash post-GELU row in smem (stride 257,
    // reusing the whole smem block) for the fused forward x-DFT.
    __syncthreads();   // everyone done reading in_s / w_s / g2_s
    float* ep = sm;    // 64 * 257 floats = 65.8 KB < FUSE_SMEM
#pragma unroll
    for (int v = 0; v < 8; v++) {
#pragma unroll
        for (int u = 0; u < 8; u++) acc[v][u] = gelu_f(acc[v][u]);
        int o = to * 8 + v;
        *(float4*)(orow + o * NPIX + x0) =
            make_float4(acc[v][0], acc[v][1], acc[v][2], acc[v][3]);
        *(float4*)(orow + o * NPIX + x0 + 4) =
            make_float4(acc[v][4], acc[v][5], acc[v][6], acc[v][7]);
#pragma unroll
        for (int u = 0; u < 8; u++) ep[o * 257 + x0 + u] = acc[v][u];
    }
    __syncthreads();
    // fused fwdX: Gx[o][t] = sum_x ep[o][x] * bFx[x][t]
    int oo = tid >> 2;          // 0..63
    int tg = tid & 3;           // 0..3 -> t = tg*8 .. tg*8+7
    float gx[8];
#pragma unroll
    for (int j = 0; j < 8; j++) gx[j] = 0.f;
    const float* ro = ep + oo * 257;
#pragma unroll 4
    for (int x = 0; x < 256; x++) {
        float a = ro[x];
        float4 c0 = __ldg((const float4*)(g_bFx + x * 32 + tg * 8));
        float4 c1 = __ldg((const float4*)(g_bFx + x * 32 + tg * 8 + 4));
        gx[0] += a * c0.x; gx[1] += a * c0.y; gx[2] += a * c0.z; gx[3] += a * c0.w;
        gx[4] += a * c1.x; gx[5] += a * c1.y; gx[6] += a * c1.z; gx[7] += a * c1.w;
    }
    float* gdst = g_Gx + ((bb * WD + oo) * 256 + y) * 32 + tg * 8;
    *(float4*)(gdst)     = make_float4(gx[0], gx[1], gx[2], gx[3]);
    *(float4*)(gdst + 4) = make_float4(gx[4], gx[5], gx[6], gx[7]);
}

// ---------------- head: fc1(64->128)+GELU, fc2(128->20), fused ----------------
#define HEAD_SMEM ((16384 + 8192 + 8192 + 2560 + 128 + 32) * 4)
__global__ void __launch_bounds__(256) k_head(const float* __restrict__ w1,
                                              const float* __restrict__ b1,
                                              const float* __restrict__ w2,
                                              const float* __restrict__ b2,
                                              float* __restrict__ out) {
    extern __shared__ float sm[];
    float* h_s   = sm;                 // 64*256
    float* w1_s  = sm + 16384;         // 128*64  [d*64+i]
    float* hid_s = w1_s + 8192;        // 32*256 chunk
    float* w2_s  = hid_s + 8192;       // 20*128  [e*128+d]
    float* b1_s  = w2_s + 2560;        // 128
    float* b2_s  = b1_s + 128;         // 20
    int bb = blockIdx.x >> 8;
    int y  = blockIdx.x & 255;
    int tid = threadIdx.x;
    for (int l = tid; l < 16384; l += 256) {
        int i = l >> 8, x = l & 255;
        h_s[l] = g_h[(bb * WD + i) * NPIX + y * 256 + x];
    }
    for (int l = tid; l < 8192; l += 256) w1_s[l] = w1[l];
    for (int l = tid; l < 2560; l += 256) w2_s[l] = w2[l];
    if (tid < 128) b1_s[tid] = b1[tid];
    if (tid < 20)  b2_s[tid] = b2[tid];
    __syncthreads();
    float acc2[COUTC];
#pragma unroll
    for (int e = 0; e < COUTC; e++) acc2[e] = 0.f;
    int tx = tid & 31, td = tid >> 5, x0 = tx * 8;
    for (int chunk = 0; chunk < 4; chunk++) {
        float a[4][8];
#pragma unroll
        for (int v = 0; v < 4; v++) {
            float bv = b1_s[chunk * 32 + td * 4 + v];
#pragma unroll
            for (int u = 0; u < 8; u++) a[v][u] = bv;
        }
        for (int i = 0; i < 64; i++) {
            float4 h0 = *(const float4*)(h_s + i * 256 + x0);
            float4 h1 = *(const float4*)(h_s + i * 256 + x0 + 4);
            float hv[8] = {h0.x, h0.y, h0.z, h0.w, h1.x, h1.y, h1.z, h1.w};
#pragma unroll
            for (int v = 0; v < 4; v++) {
                float wv = w1_s[(chunk * 32 + td * 4 + v) * 64 + i];
#pragma unroll
                for (int u = 0; u < 8; u++) a[v][u] += hv[u] * wv;
            }
        }
#pragma unroll
        for (int v = 0; v < 4; v++) {
#pragma unroll
            for (int u = 0; u < 8; u++) a[v][u] = gelu_f(a[v][u]);
            *(float4*)(hid_s + (td * 4 + v) * 256 + x0) =
                make_float4(a[v][0], a[v][1], a[v][2], a[v][3]);
            *(float4*)(hid_s + (td * 4 + v) * 256 + x0 + 4) =
                make_float4(a[v][4], a[v][5], a[v][6], a[v][7]);
        }
        __syncthreads();
        for (int c = 0; c < 32; c++) {
            float hv = hid_s[c * 256 + tid];
#pragma unroll
            for (int e = 0; e < COUTC; e++)
                acc2[e] += hv * w2_s[e * 128 + chunk * 32 + c];
        }
        __syncthreads();
    }
    float* orow = out + (bb * COUTC) * NPIX + y * 256 + tid;
#pragma unroll
    for (int e = 0; e < COUTC; e++) orow[e * NPIX] = acc2[e] + b2_s[e];
}

// ---------------- launch ------------------------------------------------------
extern "C" void kernel_launch(void* const* d_in, const int* in_sizes, int n_in,
                              void* d_out, int out_size) {
    const float* x    = (const float*)d_in[0];
    const float* w1r  = (const float*)d_in[1];
    const float* w1i  = (const float*)d_in[2];
    const float* w2r  = (const float*)d_in[3];
    const float* w2i  = (const float*)d_in[4];
    const float* pw_w = (const float*)d_in[5];
    const float* pw_b = (const float*)d_in[6];
    const float* fc0w = (const float*)d_in[7];
    const float* fc0b = (const float*)d_in[8];
    const float* fc1w = (const float*)d_in[9];
    const float* fc1b = (const float*)d_in[10];
    const float* fc2w = (const float*)d_in[11];
    const float* fc2b = (const float*)d_in[12];
    float* out = (float*)d_out;

    cudaFuncSetAttribute(k_fuse, cudaFuncAttributeMaxDynamicSharedMemorySize, FUSE_SMEM);
    cudaFuncSetAttribute(k_head, cudaFuncAttributeMaxDynamicSharedMemorySize, HEAD_SMEM);

    k_init_basis<<<32, 256>>>();
    k_lift<<<4096, 256>>>(x, fc0w, fc0b);
    k_fwdX<<<1024, 256>>>();                       // layer-0 spectral input
    for (int l = 0; l < NL; l++) {
        k_fwdY<<<1024, 128>>>();
        k_mix<<<512, 256>>>(w1r, w1i, w2r, w2i, l);
        k_invY<<<1024, 256>>>();
        // layers 0..2: GELU + fused fwdX for the next layer; layer 3: plain
        k_fuse<<<4096, 256, FUSE_SMEM>>>(pw_w, pw_b, l, (l < NL - 1) ? 1 : 0);
    }
    k_head<<<4096, 256, HEAD_SMEM>>>(fc1w, fc1b, fc2w, fc2b, out);
}

// round 5
// speedup vs baseline: 1.4162x; 1.3226x over previous
#include <cuda_runtime.h>
#include <cuda_bf16.h>
#include <math.h>

#define BB   16
#define CIN  20
#define HH   256
#define WW   256
#define WD   64
#define M1   16
#define M2   16
#define NL   4
#define FCH  128
#define COUTC 20
#define NPIX 65536

// ---------------- scratch (device globals; no allocation allowed) -------------
__device__ float g_h  [BB*WD*NPIX];          // activations, in-place per layer (268 MB)
__device__ float g_Gx [BB*WD*HH*32];         // after x-DFT: [((b*64+c)*256+y)*32]
__device__ float g_Xft[BB*WD*512*2];         // [(b*64+c)*512 + mode] complex interleaved
__device__ float g_T  [BB*WD*512*2];         // mixed modes
__device__ float g_G2 [BB*WD*HH*32];         // after inverse-y: [((b*64+o)*256+y)*32]
// basis tables
__device__ float g_bFx[WW*32];               // [x*32 + 2k(+1)]  e^{-i 2pi k x/256}
__device__ float g_bFy[HH*64];               // [y*64 + 2m(+1)]  e^{-i 2pi ky y/256}
__device__ float g_bIy[64*HH];               // TRANSPOSED [t*256+y], t=2m: cos, 2m+1: +sin
__device__ float g_bIx[32*WW];               // TRANSPOSED [t*256+x], t=2k: c*cos/65536, 2k+1: -c*sin/65536

__device__ __forceinline__ float gelu_f(float v) {
    return 0.5f * v * (1.0f + erff(v * 0.70710678118654752440f));
}

__device__ __forceinline__ void split_bf(float v, __nv_bfloat16& hi, __nv_bfloat16& lo) {
    hi = __float2bfloat16_rn(v);
    lo = __float2bfloat16_rn(v - __bfloat162float(hi));
}

__device__ __forceinline__ unsigned ld32(const __nv_bfloat16* p) {
    return *(const unsigned*)p;
}

__device__ __forceinline__ void mma_bf16(float c[4], unsigned a0, unsigned a1,
                                         unsigned a2, unsigned a3,
                                         unsigned b0, unsigned b1) {
    asm volatile(
        "mma.sync.aligned.m16n8k16.row.col.f32.bf16.bf16.f32 "
        "{%0,%1,%2,%3}, {%4,%5,%6,%7}, {%8,%9}, {%0,%1,%2,%3};"
        : "+f"(c[0]), "+f"(c[1]), "+f"(c[2]), "+f"(c[3])
        : "r"(a0), "r"(a1), "r"(a2), "r"(a3), "r"(b0), "r"(b1));
}

// ---------------- init basis --------------------------------------------------
__global__ void k_init_basis() {
    int t = blockIdx.x * blockDim.x + threadIdx.x;
    if (t < WW * M2) {
        int x = t >> 4, k = t & 15;
        double ang = (double)(k * x) / 128.0;   // theta / pi
        double s, c; sincospi(ang, &s, &c);
        g_bFx[x * 32 + 2 * k]     = (float)c;
        g_bFx[x * 32 + 2 * k + 1] = (float)(-s);
        double cc = (k == 0) ? 1.0 : 2.0;
        g_bIx[(2 * k) * WW + x]     = (float)( cc * c / 65536.0);
        g_bIx[(2 * k + 1) * WW + x] = (float)(-cc * s / 65536.0);
    }
    if (t < HH * 32) {
        int y = t >> 5, m = t & 31;
        int ky = (m < 16) ? m : (m + 224);
        double ang = (double)(ky * y) / 128.0;
        double s, c; sincospi(ang, &s, &c);
        g_bFy[y * 64 + 2 * m]     = (float)c;
        g_bFy[y * 64 + 2 * m + 1] = (float)(-s);
        g_bIy[(2 * m) * HH + y]     = (float)c;
        g_bIy[(2 * m + 1) * HH + y] = (float)s;
    }
}

// ---------------- lift: h = fc0(x) -------------------------------------------
__global__ void __launch_bounds__(256) k_lift(const float* __restrict__ x,
                                              const float* __restrict__ w,
                                              const float* __restrict__ b) {
    __shared__ float ws[WD * CIN];
    __shared__ float bs[WD];
    int tid = threadIdx.x;
    for (int i = tid; i < WD * CIN; i += 256) ws[i] = w[i];
    if (tid < WD) bs[tid] = b[tid];
    __syncthreads();
    int pix = blockIdx.x * 256 + tid;
    int bb = pix >> 16;
    int p  = pix & 65535;
    float in[CIN];
#pragma unroll
    for (int c = 0; c < CIN; c++) in[c] = x[(bb * CIN + c) * NPIX + p];
#pragma unroll 4
    for (int d = 0; d < WD; d++) {
        float acc = bs[d];
#pragma unroll
        for (int c = 0; c < CIN; c++) acc += in[c] * ws[d * CIN + c];
        g_h[(bb * WD + d) * NPIX + p] = acc;
    }
}

// ---------------- forward DFT along x: Gx[R,32] = h[R,256] * Bx[256,32] -------
__global__ void __launch_bounds__(256) k_fwdX() {
    __shared__ float As[256 * 33];
    __shared__ float Bs[32 * 33];
    int rowbase = blockIdx.x * 256;
    int tid = threadIdx.x;
    int ri = tid >> 3;   // 0..31  (rows ri + 32j)
    int ci = tid & 7;    // 0..7   (cols ci*4 .. ci*4+3)
    float acc[8][4];
#pragma unroll
    for (int j = 0; j < 8; j++)
#pragma unroll
        for (int c = 0; c < 4; c++) acc[j][c] = 0.f;
    for (int xc = 0; xc < 8; xc++) {
        if (xc) __syncthreads();
        for (int l = tid; l < 8192; l += 256) {
            int rr = l >> 5, xx = l & 31;
            As[rr * 33 + xx] = g_h[(rowbase + rr) * 256 + xc * 32 + xx];
        }
        for (int l = tid; l < 1024; l += 256) {
            int xx = l >> 5, t = l & 31;
            Bs[xx * 33 + t] = g_bFx[(xc * 32 + xx) * 32 + t];
        }
        __syncthreads();
#pragma unroll 4
        for (int xx = 0; xx < 32; xx++) {
            float b0 = Bs[xx * 33 + ci * 4 + 0];
            float b1 = Bs[xx * 33 + ci * 4 + 1];
            float b2 = Bs[xx * 33 + ci * 4 + 2];
            float b3 = Bs[xx * 33 + ci * 4 + 3];
#pragma unroll
            for (int j = 0; j < 8; j++) {
                float a = As[(ri + 32 * j) * 33 + xx];
                acc[j][0] += a * b0; acc[j][1] += a * b1;
                acc[j][2] += a * b2; acc[j][3] += a * b3;
            }
        }
    }
#pragma unroll
    for (int j = 0; j < 8; j++) {
        int row = rowbase + ri + 32 * j;
        *(float4*)(g_Gx + row * 32 + ci * 4) =
            make_float4(acc[j][0], acc[j][1], acc[j][2], acc[j][3]);
    }
}

// ---------------- forward DFT along y (256 -> 32 modes), complex --------------
__global__ void __launch_bounds__(512) k_fwdY() {
    __shared__ float s[HH * 32];   // 32 KB
    int bc = blockIdx.x;
    const float* src = g_Gx + bc * HH * 32;
    for (int l = threadIdx.x; l < HH * 32; l += 512) s[l] = src[l];
    __syncthreads();
    int t = threadIdx.x;          // mode = m*16 + k
    int m = t >> 4, k = t & 15;
    float re[4] = {0, 0, 0, 0}, im[4] = {0, 0, 0, 0};
    const float* wb = g_bFy + 2 * m;
    for (int y = 0; y < HH; y += 4) {
#pragma unroll
        for (int q = 0; q < 4; q++) {
            float2 g = *(const float2*)(s + (y + q) * 32 + 2 * k);
            float2 w = *(const float2*)(wb + (y + q) * 64);
            re[q] += g.x * w.x - g.y * w.y;
            im[q] += g.x * w.y + g.y * w.x;
        }
    }
    float rr = (re[0] + re[1]) + (re[2] + re[3]);
    float ii = (im[0] + im[1]) + (im[2] + im[3]);
    *(float2*)(g_Xft + (bc * 512 + t) * 2) = make_float2(rr, ii);
}

// ---------------- channel mix per mode: T[b,o] = sum_i X[b,i] * W[i,o] --------
__global__ void __launch_bounds__(256) k_mix(const float* __restrict__ w1r,
                                             const float* __restrict__ w1i,
                                             const float* __restrict__ w2r,
                                             const float* __restrict__ w2i,
                                             int layer) {
    __shared__ float Ws[WD * WD * 2];   // 32 KB, [ (i*64+o)*2 ]
    __shared__ float Xs[BB * WD * 2];   // 8 KB,  [ (b*64+i)*2 ]
    int mode = blockIdx.x;              // 0..511
    int m = mode >> 4;
    const float* wr; const float* wi; int off;
    if (m < 16) { wr = w1r; wi = w1i; off = mode; }
    else        { wr = w2r; wi = w2i; off = mode - 256; }
    int lbase = layer * WD * WD * 256;
    for (int l = threadIdx.x; l < WD * WD; l += 256) {
        Ws[l * 2]     = wr[lbase + l * 256 + off];
        Ws[l * 2 + 1] = wi[lbase + l * 256 + off];
    }
    for (int l = threadIdx.x; l < BB * WD; l += 256) {
        float2 v = *(const float2*)(g_Xft + (l * 512 + mode) * 2);
        *(float2*)(Xs + l * 2) = v;
    }
    __syncthreads();
    int o  = threadIdx.x & 63;
    int bq = threadIdx.x >> 6;    // 0..3 -> b = bq*4 + q
    float ar[4] = {0, 0, 0, 0}, ai[4] = {0, 0, 0, 0};
    for (int i = 0; i < WD; i++) {
        float2 w = *(const float2*)(Ws + (i * 64 + o) * 2);
#pragma unroll
        for (int q = 0; q < 4; q++) {
            float2 xv = *(const float2*)(Xs + ((bq * 4 + q) * 64 + i) * 2);
            ar[q] += xv.x * w.x - xv.y * w.y;
            ai[q] += xv.x * w.y + xv.y * w.x;
        }
    }
#pragma unroll
    for (int q = 0; q < 4; q++) {
        int b = bq * 4 + q;
        *(float2*)(g_T + ((b * 64 + o) * 512 + mode) * 2) = make_float2(ar[q], ai[q]);
    }
}

// ---------------- inverse DFT along y (32 modes -> 256), complex --------------
__global__ void __launch_bounds__(256) k_invY() {
    __shared__ float Ts[1024];
    __shared__ float smt[256 * 33];
    int bo = blockIdx.x;
    for (int l = threadIdx.x; l < 1024; l += 256) Ts[l] = g_T[bo * 1024 + l];
    __syncthreads();
    int y = threadIdx.x;
    float acc[32];
#pragma unroll
    for (int i = 0; i < 32; i++) acc[i] = 0.f;
#pragma unroll 2
    for (int m = 0; m < 32; m++) {
        float cr = g_bIy[(2 * m) * HH + y];
        float ci = g_bIy[(2 * m + 1) * HH + y];
#pragma unroll
        for (int k = 0; k < 16; k++) {
            float tr = Ts[(m * 16 + k) * 2], ti = Ts[(m * 16 + k) * 2 + 1];
            acc[2 * k]     += tr * cr - ti * ci;
            acc[2 * k + 1] += tr * ci + ti * cr;
        }
    }
#pragma unroll
    for (int u = 0; u < 32; u++) smt[y * 33 + u] = acc[u];
    __syncthreads();
    float* dst = g_G2 + bo * 8192;
    for (int l = threadIdx.x; l < 8192; l += 256)
        dst[l] = smt[(l >> 5) * 33 + (l & 31)];
}

// ---------------- fused layer core as tensor-core GEMM ------------------------
// Per block (bb, y):  C[64o x 256x] = A[64 x 96] * B[96 x 256]  (+bias, +GELU)
//   A = [ pw_w[o][i] (k=0..63) | G2[o][t] (k=64..95) ]
//   B = [ h[i][x]    (k=0..63) ; bIx[t][x] (k=64..95) ]
// bf16 hi/lo split, 3 MMA passes (AhBh + AhBl + AlBh). In-place on g_h.
#define AK    96
#define KPAD  98                         // row stride in bf16 elems (49 words, 4B-aligned rows)
#define FUSE2_SMEM (2*(64*KPAD)*2 + 2*(128*KPAD)*2 + 64*4)

__global__ void __launch_bounds__(256) k_fuse_mma(const float* __restrict__ pw_w,
                                                  const float* __restrict__ pw_b,
                                                  int layer, int apply_gelu) {
    extern __shared__ char smx[];
    __nv_bfloat16* Ahs = (__nv_bfloat16*)smx;            // [64][KPAD]
    __nv_bfloat16* Als = Ahs + 64 * KPAD;
    __nv_bfloat16* Bhs = Als + 64 * KPAD;                // [128][KPAD]  (x-major, k contiguous)
    __nv_bfloat16* Bls = Bhs + 128 * KPAD;
    float* bsh = (float*)(Bls + 128 * KPAD);             // [64]

    int bb = blockIdx.x >> 8;
    int y  = blockIdx.x & 255;
    int tid = threadIdx.x;

    // ---- stage A (weights + spectral modes), once ----
    for (int l = tid; l < 64 * 64; l += 256) {
        int o = l >> 6, i = l & 63;
        float v = pw_w[(layer * WD + o) * WD + i];
        split_bf(v, Ahs[o * KPAD + i], Als[o * KPAD + i]);
    }
    for (int l = tid; l < 64 * 32; l += 256) {
        int o = l >> 5, t = l & 31;
        float v = g_G2[(bb * WD + o) * 8192 + y * 32 + t];
        split_bf(v, Ahs[o * KPAD + 64 + t], Als[o * KPAD + 64 + t]);
    }
    if (tid < WD) bsh[tid] = pw_b[layer * WD + tid];

    int wid  = tid >> 5, lane = tid & 31;
    int mw   = wid & 3;           // M tile: rows mw*16 .. +15
    int nw   = wid >> 2;          // N tile within 128-half: cols nw*64 .. +63
    int qr   = lane >> 2;         // 0..7
    int qc   = lane & 3;          // 0..3
    int r0   = mw * 16 + qr;      // C rows r0, r0+8

    for (int nh = 0; nh < 2; nh++) {
        if (nh) __syncthreads();  // prior mma reads done before restaging B
        // ---- stage B half: activations rows + inverse-x basis ----
        for (int l = tid; l < 64 * 128; l += 256) {
            int k = l >> 7, x = l & 127;
            float v = g_h[(bb * WD + k) * NPIX + y * 256 + nh * 128 + x];
            split_bf(v, Bhs[x * KPAD + k], Bls[x * KPAD + k]);
        }
        for (int l = tid; l < 32 * 128; l += 256) {
            int t = l >> 7, x = l & 127;
            float v = g_bIx[t * 256 + nh * 128 + x];
            split_bf(v, Bhs[x * KPAD + 64 + t], Bls[x * KPAD + 64 + t]);
        }
        __syncthreads();

        // ---- main loop: C[16x64 per warp] over K=96 ----
        float c[8][4];
#pragma unroll
        for (int j = 0; j < 8; j++) {
            c[j][0] = bsh[r0]; c[j][1] = bsh[r0];
            c[j][2] = bsh[r0 + 8]; c[j][3] = bsh[r0 + 8];
        }
#pragma unroll
        for (int k0 = 0; k0 < 6; k0++) {
            int kk = k0 * 16 + qc * 2;
            unsigned ah0 = ld32(Ahs + r0 * KPAD + kk);
            unsigned ah1 = ld32(Ahs + (r0 + 8) * KPAD + kk);
            unsigned ah2 = ld32(Ahs + r0 * KPAD + kk + 8);
            unsigned ah3 = ld32(Ahs + (r0 + 8) * KPAD + kk + 8);
            unsigned al0 = ld32(Als + r0 * KPAD + kk);
            unsigned al1 = ld32(Als + (r0 + 8) * KPAD + kk);
            unsigned al2 = ld32(Als + r0 * KPAD + kk + 8);
            unsigned al3 = ld32(Als + (r0 + 8) * KPAD + kk + 8);
#pragma unroll
            for (int j = 0; j < 8; j++) {
                int xc = nw * 64 + j * 8 + qr;      // B-frag col (within half)
                unsigned bh0 = ld32(Bhs + xc * KPAD + kk);
                unsigned bh1 = ld32(Bhs + xc * KPAD + kk + 8);
                unsigned bl0 = ld32(Bls + xc * KPAD + kk);
                unsigned bl1 = ld32(Bls + xc * KPAD + kk + 8);
                mma_bf16(c[j], ah0, ah1, ah2, ah3, bh0, bh1);
                mma_bf16(c[j], ah0, ah1, ah2, ah3, bl0, bl1);
                mma_bf16(c[j], al0, al1, al2, al3, bh0, bh1);
            }
        }

        // ---- epilogue: (GELU) + in-place store ----
#pragma unroll
        for (int j = 0; j < 8; j++) {
            int xg = y * 256 + nh * 128 + nw * 64 + j * 8 + qc * 2;
            float v0 = c[j][0], v1 = c[j][1], v2 = c[j][2], v3 = c[j][3];
            if (apply_gelu) {
                v0 = gelu_f(v0); v1 = gelu_f(v1);
                v2 = gelu_f(v2); v3 = gelu_f(v3);
            }
            *(float2*)(g_h + (bb * WD + r0) * NPIX + xg)     = make_float2(v0, v1);
            *(float2*)(g_h + (bb * WD + r0 + 8) * NPIX + xg) = make_float2(v2, v3);
        }
    }
}

// ---------------- head: fc1(64->128)+GELU, fc2(128->20), fused ----------------
#define HEAD_SMEM ((16384 + 8192 + 8192 + 2560 + 128 + 32) * 4)
__global__ void __launch_bounds__(256) k_head(const float* __restrict__ w1,
                                              const float* __restrict__ b1,
                                              const float* __restrict__ w2,
                                              const float* __restrict__ b2,
                                              float* __restrict__ out) {
    extern __shared__ float sm[];
    float* h_s   = sm;                 // 64*256
    float* w1_s  = sm + 16384;         // 128*64  [d*64+i]
    float* hid_s = w1_s + 8192;        // 32*256 chunk
    float* w2_s  = hid_s + 8192;       // 20*128  [e*128+d]
    float* b1_s  = w2_s + 2560;        // 128
    float* b2_s  = b1_s + 128;         // 20
    int bb = blockIdx.x >> 8;
    int y  = blockIdx.x & 255;
    int tid = threadIdx.x;
    for (int l = tid; l < 16384; l += 256) {
        int i = l >> 8, x = l & 255;
        h_s[l] = g_h[(bb * WD + i) * NPIX + y * 256 + x];
    }
    for (int l = tid; l < 8192; l += 256) w1_s[l] = w1[l];
    for (int l = tid; l < 2560; l += 256) w2_s[l] = w2[l];
    if (tid < 128) b1_s[tid] = b1[tid];
    if (tid < 20)  b2_s[tid] = b2[tid];
    __syncthreads();
    float acc2[COUTC];
#pragma unroll
    for (int e = 0; e < COUTC; e++) acc2[e] = 0.f;
    int tx = tid & 31, td = tid >> 5, x0 = tx * 8;
    for (int chunk = 0; chunk < 4; chunk++) {
        float a[4][8];
#pragma unroll
        for (int v = 0; v < 4; v++) {
            float bv = b1_s[chunk * 32 + td * 4 + v];
#pragma unroll
            for (int u = 0; u < 8; u++) a[v][u] = bv;
        }
        for (int i = 0; i < 64; i++) {
            float4 h0 = *(const float4*)(h_s + i * 256 + x0);
            float4 h1 = *(const float4*)(h_s + i * 256 + x0 + 4);
            float hv[8] = {h0.x, h0.y, h0.z, h0.w, h1.x, h1.y, h1.z, h1.w};
#pragma unroll
            for (int v = 0; v < 4; v++) {
                float wv = w1_s[(chunk * 32 + td * 4 + v) * 64 + i];
#pragma unroll
                for (int u = 0; u < 8; u++) a[v][u] += hv[u] * wv;
            }
        }
#pragma unroll
        for (int v = 0; v < 4; v++) {
#pragma unroll
            for (int u = 0; u < 8; u++) a[v][u] = gelu_f(a[v][u]);
            *(float4*)(hid_s + (td * 4 + v) * 256 + x0) =
                make_float4(a[v][0], a[v][1], a[v][2], a[v][3]);
            *(float4*)(hid_s + (td * 4 + v) * 256 + x0 + 4) =
                make_float4(a[v][4], a[v][5], a[v][6], a[v][7]);
        }
        __syncthreads();
        for (int c = 0; c < 32; c++) {
            float hv = hid_s[c * 256 + tid];
#pragma unroll
            for (int e = 0; e < COUTC; e++)
                acc2[e] += hv * w2_s[e * 128 + chunk * 32 + c];
        }
        __syncthreads();
    }
    float* orow = out + (bb * COUTC) * NPIX + y * 256 + tid;
#pragma unroll
    for (int e = 0; e < COUTC; e++) orow[e * NPIX] = acc2[e] + b2_s[e];
}

// ---------------- launch ------------------------------------------------------
extern "C" void kernel_launch(void* const* d_in, const int* in_sizes, int n_in,
                              void* d_out, int out_size) {
    const float* x    = (const float*)d_in[0];
    const float* w1r  = (const float*)d_in[1];
    const float* w1i  = (const float*)d_in[2];
    const float* w2r  = (const float*)d_in[3];
    const float* w2i  = (const float*)d_in[4];
    const float* pw_w = (const float*)d_in[5];
    const float* pw_b = (const float*)d_in[6];
    const float* fc0w = (const float*)d_in[7];
    const float* fc0b = (const float*)d_in[8];
    const float* fc1w = (const float*)d_in[9];
    const float* fc1b = (const float*)d_in[10];
    const float* fc2w = (const float*)d_in[11];
    const float* fc2b = (const float*)d_in[12];
    float* out = (float*)d_out;

    cudaFuncSetAttribute(k_fuse_mma, cudaFuncAttributeMaxDynamicSharedMemorySize, FUSE2_SMEM);
    cudaFuncSetAttribute(k_head, cudaFuncAttributeMaxDynamicSharedMemorySize, HEAD_SMEM);

    k_init_basis<<<32, 256>>>();
    k_lift<<<4096, 256>>>(x, fc0w, fc0b);
    for (int l = 0; l < NL; l++) {
        k_fwdX<<<1024, 256>>>();
        k_fwdY<<<1024, 512>>>();
        k_mix<<<512, 256>>>(w1r, w1i, w2r, w2i, l);
        k_invY<<<1024, 256>>>();
        k_fuse_mma<<<4096, 256, FUSE2_SMEM>>>(pw_w, pw_b, l, (l < NL - 1) ? 1 : 0);
    }
    k_head<<<4096, 256, HEAD_SMEM>>>(fc1w, fc1b, fc2w, fc2b, out);
}

// round 6
// speedup vs baseline: 1.4594x; 1.0304x over previous
#include <cuda_runtime.h>
#include <cuda_bf16.h>
#include <math.h>

#define BB   16
#define CIN  20
#define HH   256
#define WW   256
#define WD   64
#define M1   16
#define M2   16
#define NL   4
#define FCH  128
#define COUTC 20
#define NPIX 65536

// ---------------- scratch (device globals; no allocation allowed) -------------
__device__ float g_h  [BB*WD*NPIX];          // activations, in-place per layer (268 MB)
__device__ float g_Gx [BB*WD*HH*32];         // after x-DFT: [row=(bc*256+y)][32]
__device__ float g_Xft[BB*WD*512*2];         // [(b*64+c)*512 + mode] complex interleaved
__device__ float g_T  [BB*WD*512*2];         // mixed modes
__device__ float g_G2 [BB*WD*HH*32];         // after inverse-y: [((b*64+o)*256+y)*32]
// basis tables
__device__ float g_bFx[WW*32];               // [x*32 + 2k(+1)]  e^{-i 2pi k x/256}
__device__ float g_bFy[HH*64];               // [y*64 + 2m(+1)]  e^{-i 2pi ky y/256}
__device__ float g_bIy[64*HH];               // TRANSPOSED [t*256+y]
__device__ float g_bIx[32*WW];               // TRANSPOSED [t*256+x], scaled 1/65536, k=0 weight 1, else 2

__device__ __forceinline__ float gelu_f(float v) {
    return 0.5f * v * (1.0f + erff(v * 0.70710678118654752440f));
}

__device__ __forceinline__ void split_bf(float v, __nv_bfloat16& hi, __nv_bfloat16& lo) {
    hi = __float2bfloat16_rn(v);
    lo = __float2bfloat16_rn(v - __bfloat162float(hi));
}

__device__ __forceinline__ unsigned ld32(const __nv_bfloat16* p) {
    return *(const unsigned*)p;
}

__device__ __forceinline__ void mma_bf16(float c[4], unsigned a0, unsigned a1,
                                         unsigned a2, unsigned a3,
                                         unsigned b0, unsigned b1) {
    asm volatile(
        "mma.sync.aligned.m16n8k16.row.col.f32.bf16.bf16.f32 "
        "{%0,%1,%2,%3}, {%4,%5,%6,%7}, {%8,%9}, {%0,%1,%2,%3};"
        : "+f"(c[0]), "+f"(c[1]), "+f"(c[2]), "+f"(c[3])
        : "r"(a0), "r"(a1), "r"(a2), "r"(a3), "r"(b0), "r"(b1));
}

// ---------------- init basis --------------------------------------------------
__global__ void k_init_basis() {
    int t = blockIdx.x * blockDim.x + threadIdx.x;
    if (t < WW * M2) {
        int x = t >> 4, k = t & 15;
        double ang = (double)(k * x) / 128.0;   // theta / pi
        double s, c; sincospi(ang, &s, &c);
        g_bFx[x * 32 + 2 * k]     = (float)c;
        g_bFx[x * 32 + 2 * k + 1] = (float)(-s);
        double cc = (k == 0) ? 1.0 : 2.0;
        g_bIx[(2 * k) * WW + x]     = (float)( cc * c / 65536.0);
        g_bIx[(2 * k + 1) * WW + x] = (float)(-cc * s / 65536.0);
    }
    if (t < HH * 32) {
        int y = t >> 5, m = t & 31;
        int ky = (m < 16) ? m : (m + 224);
        double ang = (double)(ky * y) / 128.0;
        double s, c; sincospi(ang, &s, &c);
        g_bFy[y * 64 + 2 * m]     = (float)c;
        g_bFy[y * 64 + 2 * m + 1] = (float)(-s);
        g_bIy[(2 * m) * HH + y]     = (float)c;
        g_bIy[(2 * m + 1) * HH + y] = (float)s;
    }
}

// ---------------- lift: h = fc0(x) -------------------------------------------
__global__ void __launch_bounds__(256) k_lift(const float* __restrict__ x,
                                              const float* __restrict__ w,
                                              const float* __restrict__ b) {
    __shared__ float ws[WD * CIN];
    __shared__ float bs[WD];
    int tid = threadIdx.x;
    for (int i = tid; i < WD * CIN; i += 256) ws[i] = w[i];
    if (tid < WD) bs[tid] = b[tid];
    __syncthreads();
    int pix = blockIdx.x * 256 + tid;
    int bb = pix >> 16;
    int p  = pix & 65535;
    float in[CIN];
#pragma unroll
    for (int c = 0; c < CIN; c++) in[c] = x[(bb * CIN + c) * NPIX + p];
#pragma unroll 4
    for (int d = 0; d < WD; d++) {
        float acc = bs[d];
#pragma unroll
        for (int c = 0; c < CIN; c++) acc += in[c] * ws[d * CIN + c];
        g_h[(bb * WD + d) * NPIX + p] = acc;
    }
}

// ---------------- forward DFT along x via tensor cores ------------------------
// Per block: C[128 rows x 32 modes] = A[128 x 256] * B[256 x 32], K chunked by 64.
#define XKP 66
#define XBP 258
#define FWDX2_SMEM (2*(128*XKP)*2 + 2*(32*XBP)*2)
__global__ void __launch_bounds__(256) k_fwdX_mma() {
    extern __shared__ char smx[];
    __nv_bfloat16* Ah = (__nv_bfloat16*)smx;         // [128][XKP]
    __nv_bfloat16* Al = Ah + 128 * XKP;
    __nv_bfloat16* Bh = Al + 128 * XKP;              // [32 modes][XBP] full K
    __nv_bfloat16* Bl = Bh + 32 * XBP;
    int rowbase = blockIdx.x * 128;
    int tid = threadIdx.x;
    // stage full B basis (transposed: [t][x]) once
    for (int l = tid; l < 32 * 256; l += 256) {
        int t = l & 31, x = l >> 5;
        split_bf(g_bFx[x * 32 + t], Bh[t * XBP + x], Bl[t * XBP + x]);
    }
    int wid = tid >> 5, lane = tid & 31;
    int qr = lane >> 2, qc = lane & 3;
    int r0 = wid * 16 + qr;
    float c[4][4];
#pragma unroll
    for (int j = 0; j < 4; j++)
#pragma unroll
        for (int q = 0; q < 4; q++) c[j][q] = 0.f;
    for (int kc = 0; kc < 4; kc++) {
        __syncthreads();
        for (int l = tid; l < 128 * 64; l += 256) {
            int r = l >> 6, k = l & 63;
            split_bf(g_h[(rowbase + r) * 256 + kc * 64 + k],
                     Ah[r * XKP + k], Al[r * XKP + k]);
        }
        __syncthreads();
#pragma unroll
        for (int k0 = 0; k0 < 4; k0++) {
            int kk = k0 * 16 + qc * 2;
            unsigned ah0 = ld32(Ah + r0 * XKP + kk);
            unsigned ah1 = ld32(Ah + (r0 + 8) * XKP + kk);
            unsigned ah2 = ld32(Ah + r0 * XKP + kk + 8);
            unsigned ah3 = ld32(Ah + (r0 + 8) * XKP + kk + 8);
            unsigned al0 = ld32(Al + r0 * XKP + kk);
            unsigned al1 = ld32(Al + (r0 + 8) * XKP + kk);
            unsigned al2 = ld32(Al + r0 * XKP + kk + 8);
            unsigned al3 = ld32(Al + (r0 + 8) * XKP + kk + 8);
            int kb = kc * 64 + kk;
#pragma unroll
            for (int j = 0; j < 4; j++) {
                int tc = j * 8 + qr;
                unsigned bh0 = ld32(Bh + tc * XBP + kb);
                unsigned bh1 = ld32(Bh + tc * XBP + kb + 8);
                unsigned bl0 = ld32(Bl + tc * XBP + kb);
                unsigned bl1 = ld32(Bl + tc * XBP + kb + 8);
                mma_bf16(c[j], ah0, ah1, ah2, ah3, bh0, bh1);
                mma_bf16(c[j], ah0, ah1, ah2, ah3, bl0, bl1);
                mma_bf16(c[j], al0, al1, al2, al3, bh0, bh1);
            }
        }
    }
#pragma unroll
    for (int j = 0; j < 4; j++) {
        int tc = j * 8 + qc * 2;
        *(float2*)(g_Gx + (rowbase + r0) * 32 + tc)     = make_float2(c[j][0], c[j][1]);
        *(float2*)(g_Gx + (rowbase + r0 + 8) * 32 + tc) = make_float2(c[j][2], c[j][3]);
    }
}

// ---------------- forward DFT along y (256 -> 32 modes), complex --------------
__global__ void __launch_bounds__(512) k_fwdY() {
    __shared__ float s[HH * 32];   // 32 KB
    int bc = blockIdx.x;
    const float* src = g_Gx + bc * HH * 32;
    for (int l = threadIdx.x; l < HH * 32; l += 512) s[l] = src[l];
    __syncthreads();
    int t = threadIdx.x;          // mode = m*16 + k
    int m = t >> 4, k = t & 15;
    float re[4] = {0, 0, 0, 0}, im[4] = {0, 0, 0, 0};
    const float* wb = g_bFy + 2 * m;
    for (int y = 0; y < HH; y += 4) {
#pragma unroll
        for (int q = 0; q < 4; q++) {
            float2 g = *(const float2*)(s + (y + q) * 32 + 2 * k);
            float2 w = *(const float2*)(wb + (y + q) * 64);
            re[q] += g.x * w.x - g.y * w.y;
            im[q] += g.x * w.y + g.y * w.x;
        }
    }
    float rr = (re[0] + re[1]) + (re[2] + re[3]);
    float ii = (im[0] + im[1]) + (im[2] + im[3]);
    *(float2*)(g_Xft + (bc * 512 + t) * 2) = make_float2(rr, ii);
}

// ---------------- channel mix per mode: T[b,o] = sum_i X[b,i] * W[i,o] --------
__global__ void __launch_bounds__(256) k_mix(const float* __restrict__ w1r,
                                             const float* __restrict__ w1i,
                                             const float* __restrict__ w2r,
                                             const float* __restrict__ w2i,
                                             int layer) {
    __shared__ float Ws[WD * WD * 2];   // 32 KB, [ (i*64+o)*2 ]
    __shared__ float Xs[BB * WD * 2];   // 8 KB,  [ (b*64+i)*2 ]
    int mode = blockIdx.x;              // 0..511
    int m = mode >> 4;
    const float* wr; const float* wi; int off;
    if (m < 16) { wr = w1r; wi = w1i; off = mode; }
    else        { wr = w2r; wi = w2i; off = mode - 256; }
    int lbase = layer * WD * WD * 256;
    for (int l = threadIdx.x; l < WD * WD; l += 256) {
        Ws[l * 2]     = wr[lbase + l * 256 + off];
        Ws[l * 2 + 1] = wi[lbase + l * 256 + off];
    }
    for (int l = threadIdx.x; l < BB * WD; l += 256) {
        float2 v = *(const float2*)(g_Xft + (l * 512 + mode) * 2);
        *(float2*)(Xs + l * 2) = v;
    }
    __syncthreads();
    int o  = threadIdx.x & 63;
    int bq = threadIdx.x >> 6;    // 0..3 -> b = bq*4 + q
    float ar[4] = {0, 0, 0, 0}, ai[4] = {0, 0, 0, 0};
    for (int i = 0; i < WD; i++) {
        float2 w = *(const float2*)(Ws + (i * 64 + o) * 2);
#pragma unroll
        for (int q = 0; q < 4; q++) {
            float2 xv = *(const float2*)(Xs + ((bq * 4 + q) * 64 + i) * 2);
            ar[q] += xv.x * w.x - xv.y * w.y;
            ai[q] += xv.x * w.y + xv.y * w.x;
        }
    }
#pragma unroll
    for (int q = 0; q < 4; q++) {
        int b = bq * 4 + q;
        *(float2*)(g_T + ((b * 64 + o) * 512 + mode) * 2) = make_float2(ar[q], ai[q]);
    }
}

// ---------------- inverse DFT along y (32 modes -> 256), complex --------------
__global__ void __launch_bounds__(256) k_invY() {
    __shared__ float Ts[1024];
    __shared__ float smt[256 * 33];
    int bo = blockIdx.x;
    for (int l = threadIdx.x; l < 1024; l += 256) Ts[l] = g_T[bo * 1024 + l];
    __syncthreads();
    int y = threadIdx.x;
    float acc[32];
#pragma unroll
    for (int i = 0; i < 32; i++) acc[i] = 0.f;
#pragma unroll 2
    for (int m = 0; m < 32; m++) {
        float cr = g_bIy[(2 * m) * HH + y];
        float ci = g_bIy[(2 * m + 1) * HH + y];
#pragma unroll
        for (int k = 0; k < 16; k++) {
            float tr = Ts[(m * 16 + k) * 2], ti = Ts[(m * 16 + k) * 2 + 1];
            acc[2 * k]     += tr * cr - ti * ci;
            acc[2 * k + 1] += tr * ci + ti * cr;
        }
    }
#pragma unroll
    for (int u = 0; u < 32; u++) smt[y * 33 + u] = acc[u];
    __syncthreads();
    float* dst = g_G2 + bo * 8192;
    for (int l = threadIdx.x; l < 8192; l += 256)
        dst[l] = smt[(l >> 5) * 33 + (l & 31)];
}

// ---------------- fused layer core as tensor-core GEMM ------------------------
#define KPAD  98
#define FUSE2_SMEM (2*(64*KPAD)*2 + 2*(128*KPAD)*2 + 64*4)
__global__ void __launch_bounds__(256) k_fuse_mma(const float* __restrict__ pw_w,
                                                  const float* __restrict__ pw_b,
                                                  int layer, int apply_gelu) {
    extern __shared__ char smx[];
    __nv_bfloat16* Ahs = (__nv_bfloat16*)smx;            // [64][KPAD]
    __nv_bfloat16* Als = Ahs + 64 * KPAD;
    __nv_bfloat16* Bhs = Als + 64 * KPAD;                // [128][KPAD]
    __nv_bfloat16* Bls = Bhs + 128 * KPAD;
    float* bsh = (float*)(Bls + 128 * KPAD);             // [64]

    int bb = blockIdx.x >> 8;
    int y  = blockIdx.x & 255;
    int tid = threadIdx.x;

    for (int l = tid; l < 64 * 64; l += 256) {
        int o = l >> 6, i = l & 63;
        float v = pw_w[(layer * WD + o) * WD + i];
        split_bf(v, Ahs[o * KPAD + i], Als[o * KPAD + i]);
    }
    for (int l = tid; l < 64 * 32; l += 256) {
        int o = l >> 5, t = l & 31;
        float v = g_G2[(bb * WD + o) * 8192 + y * 32 + t];
        split_bf(v, Ahs[o * KPAD + 64 + t], Als[o * KPAD + 64 + t]);
    }
    if (tid < WD) bsh[tid] = pw_b[layer * WD + tid];

    int wid  = tid >> 5, lane = tid & 31;
    int mw   = wid & 3;
    int nw   = wid >> 2;
    int qr   = lane >> 2;
    int qc   = lane & 3;
    int r0   = mw * 16 + qr;

    for (int nh = 0; nh < 2; nh++) {
        if (nh) __syncthreads();
        for (int l = tid; l < 64 * 128; l += 256) {
            int k = l >> 7, x = l & 127;
            float v = g_h[(bb * WD + k) * NPIX + y * 256 + nh * 128 + x];
            split_bf(v, Bhs[x * KPAD + k], Bls[x * KPAD + k]);
        }
        for (int l = tid; l < 32 * 128; l += 256) {
            int t = l >> 7, x = l & 127;
            float v = g_bIx[t * 256 + nh * 128 + x];
            split_bf(v, Bhs[x * KPAD + 64 + t], Bls[x * KPAD + 64 + t]);
        }
        __syncthreads();

        float c[8][4];
#pragma unroll
        for (int j = 0; j < 8; j++) {
            c[j][0] = bsh[r0]; c[j][1] = bsh[r0];
            c[j][2] = bsh[r0 + 8]; c[j][3] = bsh[r0 + 8];
        }
#pragma unroll
        for (int k0 = 0; k0 < 6; k0++) {
            int kk = k0 * 16 + qc * 2;
            unsigned ah0 = ld32(Ahs + r0 * KPAD + kk);
            unsigned ah1 = ld32(Ahs + (r0 + 8) * KPAD + kk);
            unsigned ah2 = ld32(Ahs + r0 * KPAD + kk + 8);
            unsigned ah3 = ld32(Ahs + (r0 + 8) * KPAD + kk + 8);
            unsigned al0 = ld32(Als + r0 * KPAD + kk);
            unsigned al1 = ld32(Als + (r0 + 8) * KPAD + kk);
            unsigned al2 = ld32(Als + r0 * KPAD + kk + 8);
            unsigned al3 = ld32(Als + (r0 + 8) * KPAD + kk + 8);
#pragma unroll
            for (int j = 0; j < 8; j++) {
                int xc = nw * 64 + j * 8 + qr;
                unsigned bh0 = ld32(Bhs + xc * KPAD + kk);
                unsigned bh1 = ld32(Bhs + xc * KPAD + kk + 8);
                unsigned bl0 = ld32(Bls + xc * KPAD + kk);
                unsigned bl1 = ld32(Bls + xc * KPAD + kk + 8);
                mma_bf16(c[j], ah0, ah1, ah2, ah3, bh0, bh1);
                mma_bf16(c[j], ah0, ah1, ah2, ah3, bl0, bl1);
                mma_bf16(c[j], al0, al1, al2, al3, bh0, bh1);
            }
        }

#pragma unroll
        for (int j = 0; j < 8; j++) {
            int xg = y * 256 + nh * 128 + nw * 64 + j * 8 + qc * 2;
            float v0 = c[j][0], v1 = c[j][1], v2 = c[j][2], v3 = c[j][3];
            if (apply_gelu) {
                v0 = gelu_f(v0); v1 = gelu_f(v1);
                v2 = gelu_f(v2); v3 = gelu_f(v3);
            }
            *(float2*)(g_h + (bb * WD + r0) * NPIX + xg)     = make_float2(v0, v1);
            *(float2*)(g_h + (bb * WD + r0 + 8) * NPIX + xg) = make_float2(v2, v3);
        }
    }
}

// ---------------- head via tensor cores ---------------------------------------
// Per block (bb,y): GEMM1 hid[128x256]=w1*h (chunked 32 rows, +bias +GELU),
// GEMM2 out[20(pad32)x256]=w2*hid accumulated across chunks.
#define K1P 66
#define K2P 130
#define HP  34
#define HEAD2_SMEM (2*(256*K1P)*2 + 2*(128*K1P)*2 + 2*(32*K2P)*2 + 2*(256*HP)*2 + (128+32)*4)
__global__ void __launch_bounds__(256) k_head_mma(const float* __restrict__ w1,
                                                  const float* __restrict__ b1,
                                                  const float* __restrict__ w2,
                                                  const float* __restrict__ b2,
                                                  float* __restrict__ out) {
    extern __shared__ char smx[];
    __nv_bfloat16* B1h = (__nv_bfloat16*)smx;        // h: [256 x][K1P i]
    __nv_bfloat16* B1l = B1h + 256 * K1P;
    __nv_bfloat16* A1h = B1l + 256 * K1P;            // w1: [128 d][K1P i]
    __nv_bfloat16* A1l = A1h + 128 * K1P;
    __nv_bfloat16* A2h = A1l + 128 * K1P;            // w2: [32 e][K2P d]
    __nv_bfloat16* A2l = A2h + 32 * K2P;
    __nv_bfloat16* Hh  = A2l + 32 * K2P;             // hid chunk: [256 x][HP d]
    __nv_bfloat16* Hl  = Hh + 256 * HP;
    float* b1s = (float*)(Hl + 256 * HP);            // [128]
    float* b2s = b1s + 128;                          // [32]

    int bb = blockIdx.x >> 8;
    int y  = blockIdx.x & 255;
    int tid = threadIdx.x;

    for (int l = tid; l < 64 * 256; l += 256) {
        int i = l >> 8, x = l & 255;
        float v = g_h[(bb * WD + i) * NPIX + y * 256 + x];
        split_bf(v, B1h[x * K1P + i], B1l[x * K1P + i]);
    }
    for (int l = tid; l < 128 * 64; l += 256) {
        int d = l >> 6, i = l & 63;
        split_bf(w1[d * 64 + i], A1h[d * K1P + i], A1l[d * K1P + i]);
    }
    for (int l = tid; l < 32 * 128; l += 256) {
        int e = l >> 7, d = l & 127;
        float v = (e < COUTC) ? w2[e * FCH + d] : 0.f;
        split_bf(v, A2h[e * K2P + d], A2l[e * K2P + d]);
    }
    if (tid < 128) b1s[tid] = b1[tid];
    if (tid < 32)  b2s[tid] = (tid < COUTC) ? b2[tid] : 0.f;
    __syncthreads();

    int wid = tid >> 5, lane = tid & 31;
    int mw = wid & 1;          // 2 m-tiles (rows 0-15 / 16-31 within chunk / within e-pad)
    int nw = wid >> 1;         // 4 n-tiles of 64 cols
    int qr = lane >> 2, qc = lane & 3;
    int r0 = mw * 16 + qr;

    float c2[8][4];
#pragma unroll
    for (int j = 0; j < 8; j++)
#pragma unroll
        for (int q = 0; q < 4; q++) c2[j][q] = 0.f;

    for (int chunk = 0; chunk < 4; chunk++) {
        // ---- GEMM1: c1[32 x 256] = w1[chunk rows] * h ----
        float c1[8][4];
        int dg0 = chunk * 32 + r0;
#pragma unroll
        for (int j = 0; j < 8; j++) {
            c1[j][0] = b1s[dg0]; c1[j][1] = b1s[dg0];
            c1[j][2] = b1s[dg0 + 8]; c1[j][3] = b1s[dg0 + 8];
        }
#pragma unroll
        for (int k0 = 0; k0 < 4; k0++) {
            int kk = k0 * 16 + qc * 2;
            unsigned ah0 = ld32(A1h + dg0 * K1P + kk);
            unsigned ah1 = ld32(A1h + (dg0 + 8) * K1P + kk);
            unsigned ah2 = ld32(A1h + dg0 * K1P + kk + 8);
            unsigned ah3 = ld32(A1h + (dg0 + 8) * K1P + kk + 8);
            unsigned al0 = ld32(A1l + dg0 * K1P + kk);
            unsigned al1 = ld32(A1l + (dg0 + 8) * K1P + kk);
            unsigned al2 = ld32(A1l + dg0 * K1P + kk + 8);
            unsigned al3 = ld32(A1l + (dg0 + 8) * K1P + kk + 8);
#pragma unroll
            for (int j = 0; j < 8; j++) {
                int xc = nw * 64 + j * 8 + qr;
                unsigned bh0 = ld32(B1h + xc * K1P + kk);
                unsigned bh1 = ld32(B1h + xc * K1P + kk + 8);
                unsigned bl0 = ld32(B1l + xc * K1P + kk);
                unsigned bl1 = ld32(B1l + xc * K1P + kk + 8);
                mma_bf16(c1[j], ah0, ah1, ah2, ah3, bh0, bh1);
                mma_bf16(c1[j], ah0, ah1, ah2, ah3, bl0, bl1);
                mma_bf16(c1[j], al0, al1, al2, al3, bh0, bh1);
            }
        }
        // GELU + stash hid chunk [x][d-local] hi/lo
#pragma unroll
        for (int j = 0; j < 8; j++) {
            int xc = nw * 64 + j * 8 + qc * 2;
            float v0 = gelu_f(c1[j][0]), v1 = gelu_f(c1[j][1]);
            float v2 = gelu_f(c1[j][2]), v3 = gelu_f(c1[j][3]);
            split_bf(v0, Hh[xc * HP + r0],           Hl[xc * HP + r0]);
            split_bf(v1, Hh[(xc + 1) * HP + r0],     Hl[(xc + 1) * HP + r0]);
            split_bf(v2, Hh[xc * HP + r0 + 8],       Hl[xc * HP + r0 + 8]);
            split_bf(v3, Hh[(xc + 1) * HP + r0 + 8], Hl[(xc + 1) * HP + r0 + 8]);
        }
        __syncthreads();
        // ---- GEMM2 accumulate: c2[32 e x 256] += w2[:, chunk] * hid ----
#pragma unroll
        for (int k0 = 0; k0 < 2; k0++) {
            int kk = k0 * 16 + qc * 2;
            int kg = chunk * 32 + kk;
            unsigned ah0 = ld32(A2h + r0 * K2P + kg);
            unsigned ah1 = ld32(A2h + (r0 + 8) * K2P + kg);
            unsigned ah2 = ld32(A2h + r0 * K2P + kg + 8);
            unsigned ah3 = ld32(A2h + (r0 + 8) * K2P + kg + 8);
            unsigned al0 = ld32(A2l + r0 * K2P + kg);
            unsigned al1 = ld32(A2l + (r0 + 8) * K2P + kg);
            unsigned al2 = ld32(A2l + r0 * K2P + kg + 8);
            unsigned al3 = ld32(A2l + (r0 + 8) * K2P + kg + 8);
#pragma unroll
            for (int j = 0; j < 8; j++) {
                int xc = nw * 64 + j * 8 + qr;
                unsigned bh0 = ld32(Hh + xc * HP + kk);
                unsigned bh1 = ld32(Hh + xc * HP + kk + 8);
                unsigned bl0 = ld32(Hl + xc * HP + kk);
                unsigned bl1 = ld32(Hl + xc * HP + kk + 8);
                mma_bf16(c2[j], ah0, ah1, ah2, ah3, bh0, bh1);
                mma_bf16(c2[j], ah0, ah1, ah2, ah3, bl0, bl1);
                mma_bf16(c2[j], al0, al1, al2, al3, bh0, bh1);
            }
        }
        __syncthreads();   // protect H before next chunk overwrite
    }

    // epilogue: bias + store rows e < 20
    int e0 = r0, e1 = r0 + 8;
#pragma unroll
    for (int j = 0; j < 8; j++) {
        int xc = nw * 64 + j * 8 + qc * 2;
        if (e0 < COUTC) {
            *(float2*)(out + (bb * COUTC + e0) * NPIX + y * 256 + xc) =
                make_float2(c2[j][0] + b2s[e0], c2[j][1] + b2s[e0]);
        }
        if (e1 < COUTC) {
            *(float2*)(out + (bb * COUTC + e1) * NPIX + y * 256 + xc) =
                make_float2(c2[j][2] + b2s[e1], c2[j][3] + b2s[e1]);
        }
    }
}

// ---------------- launch ------------------------------------------------------
extern "C" void kernel_launch(void* const* d_in, const int* in_sizes, int n_in,
                              void* d_out, int out_size) {
    const float* x    = (const float*)d_in[0];
    const float* w1r  = (const float*)d_in[1];
    const float* w1i  = (const float*)d_in[2];
    const float* w2r  = (const float*)d_in[3];
    const float* w2i  = (const float*)d_in[4];
    const float* pw_w = (const float*)d_in[5];
    const float* pw_b = (const float*)d_in[6];
    const float* fc0w = (const float*)d_in[7];
    const float* fc0b = (const float*)d_in[8];
    const float* fc1w = (const float*)d_in[9];
    const float* fc1b = (const float*)d_in[10];
    const float* fc2w = (const float*)d_in[11];
    const float* fc2b = (const float*)d_in[12];
    float* out = (float*)d_out;

    cudaFuncSetAttribute(k_fuse_mma, cudaFuncAttributeMaxDynamicSharedMemorySize, FUSE2_SMEM);
    cudaFuncSetAttribute(k_fwdX_mma, cudaFuncAttributeMaxDynamicSharedMemorySize, FWDX2_SMEM);
    cudaFuncSetAttribute(k_head_mma, cudaFuncAttributeMaxDynamicSharedMemorySize, HEAD2_SMEM);

    k_init_basis<<<32, 256>>>();
    k_lift<<<4096, 256>>>(x, fc0w, fc0b);
    for (int l = 0; l < NL; l++) {
        k_fwdX_mma<<<2048, 256, FWDX2_SMEM>>>();
        k_fwdY<<<1024, 512>>>();
        k_mix<<<512, 256>>>(w1r, w1i, w2r, w2i, l);
        k_invY<<<1024, 256>>>();
        k_fuse_mma<<<4096, 256, FUSE2_SMEM>>>(pw_w, pw_b, l, (l < NL - 1) ? 1 : 0);
    }
    k_head_mma<<<4096, 256, HEAD2_SMEM>>>(fc1w, fc1b, fc2w, fc2b, out);
}

// round 7
// speedup vs baseline: 1.4867x; 1.0187x over previous
#include <cuda_runtime.h>
#include <cuda_bf16.h>
#include <math.h>

#define BB   16
#define CIN  20
#define HH   256
#define WW   256
#define WD   64
#define M1   16
#define M2   16
#define NL   4
#define FCH  128
#define COUTC 20
#define NPIX 65536

// ---------------- scratch (device globals; no allocation allowed) -------------
__device__ float g_h  [BB*WD*NPIX];          // activations, in-place per layer (268 MB)
__device__ float g_Gx [BB*WD*HH*32];         // after x-DFT: [row=(bc*256+y)][32]
__device__ float g_Xft[BB*WD*512*2];         // [(b*64+c)*512 + mode] complex interleaved
__device__ float g_T  [BB*WD*512*2];         // mixed modes
__device__ float g_G2 [BB*WD*HH*32];         // after inverse-y: [((b*64+o)*256+y)*32]
// basis tables
__device__ float g_bFx[WW*32];               // [x*32 + 2k(+1)]  e^{-i 2pi k x/256}
__device__ float g_bFy[HH*64];               // (init only)
__device__ float g_bIy[64*HH];               // (init only)
__device__ float g_bIx[32*WW];               // TRANSPOSED [t*256+x], scaled 1/65536
// bf16 hi/lo split basis for MMA kernels
__device__ __nv_bfloat16 g_bFyA_h[64*256];   // fwdY A: row(2m)=cos, row(2m+1)=-sin, [row][y]
__device__ __nv_bfloat16 g_bFyA_l[64*256];
__device__ __nv_bfloat16 g_bIyA_h[256*64];   // invY A: [y][2m]=cos, [y][2m+1]=+sin
__device__ __nv_bfloat16 g_bIyA_l[256*64];

__device__ __forceinline__ float gelu_f(float v) {
    return 0.5f * v * (1.0f + erff(v * 0.70710678118654752440f));
}

__device__ __forceinline__ void split_bf(float v, __nv_bfloat16& hi, __nv_bfloat16& lo) {
    hi = __float2bfloat16_rn(v);
    lo = __float2bfloat16_rn(v - __bfloat162float(hi));
}

__device__ __forceinline__ unsigned ld32(const __nv_bfloat16* p) {
    return *(const unsigned*)p;
}

__device__ __forceinline__ void mma_bf16(float c[4], unsigned a0, unsigned a1,
                                         unsigned a2, unsigned a3,
                                         unsigned b0, unsigned b1) {
    asm volatile(
        "mma.sync.aligned.m16n8k16.row.col.f32.bf16.bf16.f32 "
        "{%0,%1,%2,%3}, {%4,%5,%6,%7}, {%8,%9}, {%0,%1,%2,%3};"
        : "+f"(c[0]), "+f"(c[1]), "+f"(c[2]), "+f"(c[3])
        : "r"(a0), "r"(a1), "r"(a2), "r"(a3), "r"(b0), "r"(b1));
}

// ---------------- init basis --------------------------------------------------
__global__ void k_init_basis() {
    int t = blockIdx.x * blockDim.x + threadIdx.x;
    if (t < WW * M2) {
        int x = t >> 4, k = t & 15;
        double ang = (double)(k * x) / 128.0;   // theta / pi
        double s, c; sincospi(ang, &s, &c);
        g_bFx[x * 32 + 2 * k]     = (float)c;
        g_bFx[x * 32 + 2 * k + 1] = (float)(-s);
        double cc = (k == 0) ? 1.0 : 2.0;
        g_bIx[(2 * k) * WW + x]     = (float)( cc * c / 65536.0);
        g_bIx[(2 * k + 1) * WW + x] = (float)(-cc * s / 65536.0);
    }
    if (t < HH * 32) {
        int y = t >> 5, m = t & 31;
        int ky = (m < 16) ? m : (m + 224);
        double ang = (double)(ky * y) / 128.0;
        double s, c; sincospi(ang, &s, &c);
        g_bFy[y * 64 + 2 * m]     = (float)c;
        g_bFy[y * 64 + 2 * m + 1] = (float)(-s);
        g_bIy[(2 * m) * HH + y]     = (float)c;
        g_bIy[(2 * m + 1) * HH + y] = (float)s;
        split_bf((float)c,  g_bFyA_h[(2*m)*256 + y],   g_bFyA_l[(2*m)*256 + y]);
        split_bf((float)-s, g_bFyA_h[(2*m+1)*256 + y], g_bFyA_l[(2*m+1)*256 + y]);
        split_bf((float)c,  g_bIyA_h[y*64 + 2*m],      g_bIyA_l[y*64 + 2*m]);
        split_bf((float)s,  g_bIyA_h[y*64 + 2*m+1],    g_bIyA_l[y*64 + 2*m+1]);
    }
}

// ---------------- lift: h = fc0(x) -------------------------------------------
__global__ void __launch_bounds__(256) k_lift(const float* __restrict__ x,
                                              const float* __restrict__ w,
                                              const float* __restrict__ b) {
    __shared__ float ws[WD * CIN];
    __shared__ float bs[WD];
    int tid = threadIdx.x;
    for (int i = tid; i < WD * CIN; i += 256) ws[i] = w[i];
    if (tid < WD) bs[tid] = b[tid];
    __syncthreads();
    int pix = blockIdx.x * 256 + tid;
    int bb = pix >> 16;
    int p  = pix & 65535;
    float in[CIN];
#pragma unroll
    for (int c = 0; c < CIN; c++) in[c] = x[(bb * CIN + c) * NPIX + p];
#pragma unroll 4
    for (int d = 0; d < WD; d++) {
        float acc = bs[d];
#pragma unroll
        for (int c = 0; c < CIN; c++) acc += in[c] * ws[d * CIN + c];
        g_h[(bb * WD + d) * NPIX + p] = acc;
    }
}

// ---------------- forward DFT along x via tensor cores ------------------------
#define XKP 66
#define XBP 258
#define FWDX2_SMEM (2*(128*XKP)*2 + 2*(32*XBP)*2)
__global__ void __launch_bounds__(256) k_fwdX_mma() {
    extern __shared__ char smx[];
    __nv_bfloat16* Ah = (__nv_bfloat16*)smx;         // [128][XKP]
    __nv_bfloat16* Al = Ah + 128 * XKP;
    __nv_bfloat16* Bh = Al + 128 * XKP;              // [32 modes][XBP] full K
    __nv_bfloat16* Bl = Bh + 32 * XBP;
    int rowbase = blockIdx.x * 128;
    int tid = threadIdx.x;
    for (int l = tid; l < 32 * 256; l += 256) {
        int t = l & 31, x = l >> 5;
        split_bf(g_bFx[x * 32 + t], Bh[t * XBP + x], Bl[t * XBP + x]);
    }
    int wid = tid >> 5, lane = tid & 31;
    int qr = lane >> 2, qc = lane & 3;
    int r0 = wid * 16 + qr;
    float c[4][4];
#pragma unroll
    for (int j = 0; j < 4; j++)
#pragma unroll
        for (int q = 0; q < 4; q++) c[j][q] = 0.f;
    for (int kc = 0; kc < 4; kc++) {
        __syncthreads();
        for (int l = tid; l < 128 * 64; l += 256) {
            int r = l >> 6, k = l & 63;
            split_bf(g_h[(rowbase + r) * 256 + kc * 64 + k],
                     Ah[r * XKP + k], Al[r * XKP + k]);
        }
        __syncthreads();
#pragma unroll
        for (int k0 = 0; k0 < 4; k0++) {
            int kk = k0 * 16 + qc * 2;
            unsigned ah0 = ld32(Ah + r0 * XKP + kk);
            unsigned ah1 = ld32(Ah + (r0 + 8) * XKP + kk);
            unsigned ah2 = ld32(Ah + r0 * XKP + kk + 8);
            unsigned ah3 = ld32(Ah + (r0 + 8) * XKP + kk + 8);
            unsigned al0 = ld32(Al + r0 * XKP + kk);
            unsigned al1 = ld32(Al + (r0 + 8) * XKP + kk);
            unsigned al2 = ld32(Al + r0 * XKP + kk + 8);
            unsigned al3 = ld32(Al + (r0 + 8) * XKP + kk + 8);
            int kb = kc * 64 + kk;
#pragma unroll
            for (int j = 0; j < 4; j++) {
                int tc = j * 8 + qr;
                unsigned bh0 = ld32(Bh + tc * XBP + kb);
                unsigned bh1 = ld32(Bh + tc * XBP + kb + 8);
                unsigned bl0 = ld32(Bl + tc * XBP + kb);
                unsigned bl1 = ld32(Bl + tc * XBP + kb + 8);
                mma_bf16(c[j], ah0, ah1, ah2, ah3, bh0, bh1);
                mma_bf16(c[j], ah0, ah1, ah2, ah3, bl0, bl1);
                mma_bf16(c[j], al0, al1, al2, al3, bh0, bh1);
            }
        }
    }
#pragma unroll
    for (int j = 0; j < 4; j++) {
        int tc = j * 8 + qc * 2;
        *(float2*)(g_Gx + (rowbase + r0) * 32 + tc)     = make_float2(c[j][0], c[j][1]);
        *(float2*)(g_Gx + (rowbase + r0 + 8) * 32 + tc) = make_float2(c[j][2], c[j][3]);
    }
}

// ---------------- forward DFT along y via tensor cores ------------------------
// Per block (b,c): P[64x32] = A[64x256] * B[256x32]; combine -> Xft.
#define YP 264
#define FWDY2_SMEM (2*(32*YP)*2)
__global__ void __launch_bounds__(256) k_fwdY_mma() {
    extern __shared__ char smx[];
    __nv_bfloat16* Bh = (__nv_bfloat16*)smx;     // [32 t][YP y]
    __nv_bfloat16* Bl = Bh + 32 * YP;
    float* Ps = (float*)smx;                     // overlay after mma (64*33 floats)
    int bc = blockIdx.x;
    int tid = threadIdx.x;
    const float* src = g_Gx + bc * HH * 32;
    for (int l = tid; l < 8192; l += 256) {
        int y = l >> 5, t = l & 31;
        split_bf(src[l], Bh[t * YP + y], Bl[t * YP + y]);
    }
    __syncthreads();
    int wid = tid >> 5, lane = tid & 31;
    int mw = wid & 3, nh = wid >> 2;
    int qr = lane >> 2, qc = lane & 3;
    int r0 = mw * 16 + qr;
    float c[2][4];
#pragma unroll
    for (int j = 0; j < 2; j++)
#pragma unroll
        for (int q = 0; q < 4; q++) c[j][q] = 0.f;
#pragma unroll 4
    for (int k0 = 0; k0 < 16; k0++) {
        int kk = k0 * 16 + qc * 2;
        unsigned ah0 = ld32(g_bFyA_h + r0 * 256 + kk);
        unsigned ah1 = ld32(g_bFyA_h + (r0 + 8) * 256 + kk);
        unsigned ah2 = ld32(g_bFyA_h + r0 * 256 + kk + 8);
        unsigned ah3 = ld32(g_bFyA_h + (r0 + 8) * 256 + kk + 8);
        unsigned al0 = ld32(g_bFyA_l + r0 * 256 + kk);
        unsigned al1 = ld32(g_bFyA_l + (r0 + 8) * 256 + kk);
        unsigned al2 = ld32(g_bFyA_l + r0 * 256 + kk + 8);
        unsigned al3 = ld32(g_bFyA_l + (r0 + 8) * 256 + kk + 8);
#pragma unroll
        for (int j = 0; j < 2; j++) {
            int tc = nh * 16 + j * 8 + qr;
            unsigned bh0 = ld32(Bh + tc * YP + kk);
            unsigned bh1 = ld32(Bh + tc * YP + kk + 8);
            unsigned bl0 = ld32(Bl + tc * YP + kk);
            unsigned bl1 = ld32(Bl + tc * YP + kk + 8);
            mma_bf16(c[j], ah0, ah1, ah2, ah3, bh0, bh1);
            mma_bf16(c[j], ah0, ah1, ah2, ah3, bl0, bl1);
            mma_bf16(c[j], al0, al1, al2, al3, bh0, bh1);
        }
    }
    __syncthreads();   // all mma B-reads done before overlaying Ps
#pragma unroll
    for (int j = 0; j < 2; j++) {
        int cc = nh * 16 + j * 8 + qc * 2;
        Ps[r0 * 33 + cc]           = c[j][0];
        Ps[r0 * 33 + cc + 1]       = c[j][1];
        Ps[(r0 + 8) * 33 + cc]     = c[j][2];
        Ps[(r0 + 8) * 33 + cc + 1] = c[j][3];
    }
    __syncthreads();
    for (int l = tid; l < 512; l += 256) {
        int m = l >> 4, k = l & 15;
        float re = Ps[(2 * m) * 33 + 2 * k]     - Ps[(2 * m + 1) * 33 + 2 * k + 1];
        float im = Ps[(2 * m) * 33 + 2 * k + 1] + Ps[(2 * m + 1) * 33 + 2 * k];
        *(float2*)(g_Xft + (bc * 512 + l) * 2) = make_float2(re, im);
    }
}

// ---------------- channel mix per mode: T[b,o] = sum_i X[b,i] * W[i,o] --------
__global__ void __launch_bounds__(256) k_mix(const float* __restrict__ w1r,
                                             const float* __restrict__ w1i,
                                             const float* __restrict__ w2r,
                                             const float* __restrict__ w2i,
                                             int layer) {
    __shared__ float Ws[WD * WD * 2];
    __shared__ float Xs[BB * WD * 2];
    int mode = blockIdx.x;
    int m = mode >> 4;
    const float* wr; const float* wi; int off;
    if (m < 16) { wr = w1r; wi = w1i; off = mode; }
    else        { wr = w2r; wi = w2i; off = mode - 256; }
    int lbase = layer * WD * WD * 256;
    for (int l = threadIdx.x; l < WD * WD; l += 256) {
        Ws[l * 2]     = wr[lbase + l * 256 + off];
        Ws[l * 2 + 1] = wi[lbase + l * 256 + off];
    }
    for (int l = threadIdx.x; l < BB * WD; l += 256) {
        float2 v = *(const float2*)(g_Xft + (l * 512 + mode) * 2);
        *(float2*)(Xs + l * 2) = v;
    }
    __syncthreads();
    int o  = threadIdx.x & 63;
    int bq = threadIdx.x >> 6;
    float ar[4] = {0, 0, 0, 0}, ai[4] = {0, 0, 0, 0};
    for (int i = 0; i < WD; i++) {
        float2 w = *(const float2*)(Ws + (i * 64 + o) * 2);
#pragma unroll
        for (int q = 0; q < 4; q++) {
            float2 xv = *(const float2*)(Xs + ((bq * 4 + q) * 64 + i) * 2);
            ar[q] += xv.x * w.x - xv.y * w.y;
            ai[q] += xv.x * w.y + xv.y * w.x;
        }
    }
#pragma unroll
    for (int q = 0; q < 4; q++) {
        int b = bq * 4 + q;
        *(float2*)(g_T + ((b * 64 + o) * 512 + mode) * 2) = make_float2(ar[q], ai[q]);
    }
}

// ---------------- inverse DFT along y via tensor cores ------------------------
// Per block (b,o): C[256y x 64] = A[256x64] * B_embed[64x64]; C cols == g_G2 layout.
#define IKP 66
#define INVY2_SMEM (1024*4 + 2*(64*IKP)*2)
__global__ void __launch_bounds__(256) k_invY_mma() {
    extern __shared__ char smx[];
    float* Ts = (float*)smx;                             // [1024]
    __nv_bfloat16* Bh = (__nv_bfloat16*)(smx + 4096);    // [64 col][IKP k]
    __nv_bfloat16* Bl = Bh + 64 * IKP;
    int bo = blockIdx.x;
    int tid = threadIdx.x;
    for (int l = tid; l < 1024; l += 256) Ts[l] = g_T[bo * 1024 + l];
    __syncthreads();
    for (int l = tid; l < 4096; l += 256) {
        int col = l >> 6, k = l & 63;
        int k2 = col >> 1, m = k >> 1;
        float Tr = Ts[(m * 16 + k2) * 2];
        float Ti = Ts[(m * 16 + k2) * 2 + 1];
        float v = (col & 1) ? ((k & 1) ? Tr : Ti) : ((k & 1) ? -Ti : Tr);
        split_bf(v, Bh[col * IKP + k], Bl[col * IKP + k]);
    }
    __syncthreads();
    int wid = tid >> 5, lane = tid & 31;
    int qr = lane >> 2, qc = lane & 3;
    float c[2][8][4];
#pragma unroll
    for (int mt = 0; mt < 2; mt++)
#pragma unroll
        for (int j = 0; j < 8; j++)
#pragma unroll
            for (int q = 0; q < 4; q++) c[mt][j][q] = 0.f;
#pragma unroll
    for (int k0 = 0; k0 < 4; k0++) {
        int kk = k0 * 16 + qc * 2;
        unsigned bh0[8], bh1[8], bl0[8], bl1[8];
#pragma unroll
        for (int j = 0; j < 8; j++) {
            int tc = j * 8 + qr;
            bh0[j] = ld32(Bh + tc * IKP + kk);
            bh1[j] = ld32(Bh + tc * IKP + kk + 8);
            bl0[j] = ld32(Bl + tc * IKP + kk);
            bl1[j] = ld32(Bl + tc * IKP + kk + 8);
        }
#pragma unroll
        for (int mt = 0; mt < 2; mt++) {
            int r0 = wid * 32 + mt * 16 + qr;
            unsigned ah0 = ld32(g_bIyA_h + r0 * 64 + kk);
            unsigned ah1 = ld32(g_bIyA_h + (r0 + 8) * 64 + kk);
            unsigned ah2 = ld32(g_bIyA_h + r0 * 64 + kk + 8);
            unsigned ah3 = ld32(g_bIyA_h + (r0 + 8) * 64 + kk + 8);
            unsigned al0 = ld32(g_bIyA_l + r0 * 64 + kk);
            unsigned al1 = ld32(g_bIyA_l + (r0 + 8) * 64 + kk);
            unsigned al2 = ld32(g_bIyA_l + r0 * 64 + kk + 8);
            unsigned al3 = ld32(g_bIyA_l + (r0 + 8) * 64 + kk + 8);
#pragma unroll
            for (int j = 0; j < 8; j++) {
                mma_bf16(c[mt][j], ah0, ah1, ah2, ah3, bh0[j], bh1[j]);
                mma_bf16(c[mt][j], ah0, ah1, ah2, ah3, bl0[j], bl1[j]);
                mma_bf16(c[mt][j], al0, al1, al2, al3, bh0[j], bh1[j]);
            }
        }
    }
    float* dst = g_G2 + bo * 8192;
#pragma unroll
    for (int mt = 0; mt < 2; mt++) {
        int r0 = wid * 32 + mt * 16 + qr;
#pragma unroll
        for (int j = 0; j < 8; j++) {
            int cc = j * 8 + qc * 2;
            *(float2*)(dst + r0 * 32 + cc)       = make_float2(c[mt][j][0], c[mt][j][1]);
            *(float2*)(dst + (r0 + 8) * 32 + cc) = make_float2(c[mt][j][2], c[mt][j][3]);
        }
    }
}

// ---------------- fused layer core as tensor-core GEMM ------------------------
#define KPAD  98
#define FUSE2_SMEM (2*(64*KPAD)*2 + 2*(128*KPAD)*2 + 64*4)
__global__ void __launch_bounds__(256) k_fuse_mma(const float* __restrict__ pw_w,
                                                  const float* __restrict__ pw_b,
                                                  int layer, int apply_gelu) {
    extern __shared__ char smx[];
    __nv_bfloat16* Ahs = (__nv_bfloat16*)smx;
    __nv_bfloat16* Als = Ahs + 64 * KPAD;
    __nv_bfloat16* Bhs = Als + 64 * KPAD;
    __nv_bfloat16* Bls = Bhs + 128 * KPAD;
    float* bsh = (float*)(Bls + 128 * KPAD);

    int bb = blockIdx.x >> 8;
    int y  = blockIdx.x & 255;
    int tid = threadIdx.x;

    for (int l = tid; l < 64 * 64; l += 256) {
        int o = l >> 6, i = l & 63;
        float v = pw_w[(layer * WD + o) * WD + i];
        split_bf(v, Ahs[o * KPAD + i], Als[o * KPAD + i]);
    }
    for (int l = tid; l < 64 * 32; l += 256) {
        int o = l >> 5, t = l & 31;
        float v = g_G2[(bb * WD + o) * 8192 + y * 32 + t];
        split_bf(v, Ahs[o * KPAD + 64 + t], Als[o * KPAD + 64 + t]);
    }
    if (tid < WD) bsh[tid] = pw_b[layer * WD + tid];

    int wid  = tid >> 5, lane = tid & 31;
    int mw   = wid & 3;
    int nw   = wid >> 2;
    int qr   = lane >> 2;
    int qc   = lane & 3;
    int r0   = mw * 16 + qr;

    for (int nh = 0; nh < 2; nh++) {
        if (nh) __syncthreads();
        for (int l = tid; l < 64 * 128; l += 256) {
            int k = l >> 7, x = l & 127;
            float v = g_h[(bb * WD + k) * NPIX + y * 256 + nh * 128 + x];
            split_bf(v, Bhs[x * KPAD + k], Bls[x * KPAD + k]);
        }
        for (int l = tid; l < 32 * 128; l += 256) {
            int t = l >> 7, x = l & 127;
            float v = g_bIx[t * 256 + nh * 128 + x];
            split_bf(v, Bhs[x * KPAD + 64 + t], Bls[x * KPAD + 64 + t]);
        }
        __syncthreads();

        float c[8][4];
#pragma unroll
        for (int j = 0; j < 8; j++) {
            c[j][0] = bsh[r0]; c[j][1] = bsh[r0];
            c[j][2] = bsh[r0 + 8]; c[j][3] = bsh[r0 + 8];
        }
#pragma unroll
        for (int k0 = 0; k0 < 6; k0++) {
            int kk = k0 * 16 + qc * 2;
            unsigned ah0 = ld32(Ahs + r0 * KPAD + kk);
            unsigned ah1 = ld32(Ahs + (r0 + 8) * KPAD + kk);
            unsigned ah2 = ld32(Ahs + r0 * KPAD + kk + 8);
            unsigned ah3 = ld32(Ahs + (r0 + 8) * KPAD + kk + 8);
            unsigned al0 = ld32(Als + r0 * KPAD + kk);
            unsigned al1 = ld32(Als + (r0 + 8) * KPAD + kk);
            unsigned al2 = ld32(Als + r0 * KPAD + kk + 8);
            unsigned al3 = ld32(Als + (r0 + 8) * KPAD + kk + 8);
#pragma unroll
            for (int j = 0; j < 8; j++) {
                int xc = nw * 64 + j * 8 + qr;
                unsigned bh0 = ld32(Bhs + xc * KPAD + kk);
                unsigned bh1 = ld32(Bhs + xc * KPAD + kk + 8);
                unsigned bl0 = ld32(Bls + xc * KPAD + kk);
                unsigned bl1 = ld32(Bls + xc * KPAD + kk + 8);
                mma_bf16(c[j], ah0, ah1, ah2, ah3, bh0, bh1);
                mma_bf16(c[j], ah0, ah1, ah2, ah3, bl0, bl1);
                mma_bf16(c[j], al0, al1, al2, al3, bh0, bh1);
            }
        }

#pragma unroll
        for (int j = 0; j < 8; j++) {
            int xg = y * 256 + nh * 128 + nw * 64 + j * 8 + qc * 2;
            float v0 = c[j][0], v1 = c[j][1], v2 = c[j][2], v3 = c[j][3];
            if (apply_gelu) {
                v0 = gelu_f(v0); v1 = gelu_f(v1);
                v2 = gelu_f(v2); v3 = gelu_f(v3);
            }
            *(float2*)(g_h + (bb * WD + r0) * NPIX + xg)     = make_float2(v0, v1);
            *(float2*)(g_h + (bb * WD + r0 + 8) * NPIX + xg) = make_float2(v2, v3);
        }
    }
}

// ---------------- head via tensor cores ---------------------------------------
#define K1P 66
#define K2P 130
#define HP  34
#define HEAD2_SMEM (2*(256*K1P)*2 + 2*(128*K1P)*2 + 2*(32*K2P)*2 + 2*(256*HP)*2 + (128+32)*4)
__global__ void __launch_bounds__(256) k_head_mma(const float* __restrict__ w1,
                                                  const float* __restrict__ b1,
                                                  const float* __restrict__ w2,
                                                  const float* __restrict__ b2,
                                                  float* __restrict__ out) {
    extern __shared__ char smx[];
    __nv_bfloat16* B1h = (__nv_bfloat16*)smx;
    __nv_bfloat16* B1l = B1h + 256 * K1P;
    __nv_bfloat16* A1h = B1l + 256 * K1P;
    __nv_bfloat16* A1l = A1h + 128 * K1P;
    __nv_bfloat16* A2h = A1l + 128 * K1P;
    __nv_bfloat16* A2l = A2h + 32 * K2P;
    __nv_bfloat16* Hh  = A2l + 32 * K2P;
    __nv_bfloat16* Hl  = Hh + 256 * HP;
    float* b1s = (float*)(Hl + 256 * HP);
    float* b2s = b1s + 128;

    int bb = blockIdx.x >> 8;
    int y  = blockIdx.x & 255;
    int tid = threadIdx.x;

    for (int l = tid; l < 64 * 256; l += 256) {
        int i = l >> 8, x = l & 255;
        float v = g_h[(bb * WD + i) * NPIX + y * 256 + x];
        split_bf(v, B1h[x * K1P + i], B1l[x * K1P + i]);
    }
    for (int l = tid; l < 128 * 64; l += 256) {
        int d = l >> 6, i = l & 63;
        split_bf(w1[d * 64 + i], A1h[d * K1P + i], A1l[d * K1P + i]);
    }
    for (int l = tid; l < 32 * 128; l += 256) {
        int e = l >> 7, d = l & 127;
        float v = (e < COUTC) ? w2[e * FCH + d] : 0.f;
        split_bf(v, A2h[e * K2P + d], A2l[e * K2P + d]);
    }
    if (tid < 128) b1s[tid] = b1[tid];
    if (tid < 32)  b2s[tid] = (tid < COUTC) ? b2[tid] : 0.f;
    __syncthreads();

    int wid = tid >> 5, lane = tid & 31;
    int mw = wid & 1;
    int nw = wid >> 1;
    int qr = lane >> 2, qc = lane & 3;
    int r0 = mw * 16 + qr;

    float c2[8][4];
#pragma unroll
    for (int j = 0; j < 8; j++)
#pragma unroll
        for (int q = 0; q < 4; q++) c2[j][q] = 0.f;

    for (int chunk = 0; chunk < 4; chunk++) {
        float c1[8][4];
        int dg0 = chunk * 32 + r0;
#pragma unroll
        for (int j = 0; j < 8; j++) {
            c1[j][0] = b1s[dg0]; c1[j][1] = b1s[dg0];
            c1[j][2] = b1s[dg0 + 8]; c1[j][3] = b1s[dg0 + 8];
        }
#pragma unroll
        for (int k0 = 0; k0 < 4; k0++) {
            int kk = k0 * 16 + qc * 2;
            unsigned ah0 = ld32(A1h + dg0 * K1P + kk);
            unsigned ah1 = ld32(A1h + (dg0 + 8) * K1P + kk);
            unsigned ah2 = ld32(A1h + dg0 * K1P + kk + 8);
            unsigned ah3 = ld32(A1h + (dg0 + 8) * K1P + kk + 8);
            unsigned al0 = ld32(A1l + dg0 * K1P + kk);
            unsigned al1 = ld32(A1l + (dg0 + 8) * K1P + kk);
            unsigned al2 = ld32(A1l + dg0 * K1P + kk + 8);
            unsigned al3 = ld32(A1l + (dg0 + 8) * K1P + kk + 8);
#pragma unroll
            for (int j = 0; j < 8; j++) {
                int xc = nw * 64 + j * 8 + qr;
                unsigned bh0 = ld32(B1h + xc * K1P + kk);
                unsigned bh1 = ld32(B1h + xc * K1P + kk + 8);
                unsigned bl0 = ld32(B1l + xc * K1P + kk);
                unsigned bl1 = ld32(B1l + xc * K1P + kk + 8);
                mma_bf16(c1[j], ah0, ah1, ah2, ah3, bh0, bh1);
                mma_bf16(c1[j], ah0, ah1, ah2, ah3, bl0, bl1);
                mma_bf16(c1[j], al0, al1, al2, al3, bh0, bh1);
            }
        }
#pragma unroll
        for (int j = 0; j < 8; j++) {
            int xc = nw * 64 + j * 8 + qc * 2;
            float v0 = gelu_f(c1[j][0]), v1 = gelu_f(c1[j][1]);
            float v2 = gelu_f(c1[j][2]), v3 = gelu_f(c1[j][3]);
            split_bf(v0, Hh[xc * HP + r0],           Hl[xc * HP + r0]);
            split_bf(v1, Hh[(xc + 1) * HP + r0],     Hl[(xc + 1) * HP + r0]);
            split_bf(v2, Hh[xc * HP + r0 + 8],       Hl[xc * HP + r0 + 8]);
            split_bf(v3, Hh[(xc + 1) * HP + r0 + 8], Hl[(xc + 1) * HP + r0 + 8]);
        }
        __syncthreads();
#pragma unroll
        for (int k0 = 0; k0 < 2; k0++) {
            int kk = k0 * 16 + qc * 2;
            int kg = chunk * 32 + kk;
            unsigned ah0 = ld32(A2h + r0 * K2P + kg);
            unsigned ah1 = ld32(A2h + (r0 + 8) * K2P + kg);
            unsigned ah2 = ld32(A2h + r0 * K2P + kg + 8);
            unsigned ah3 = ld32(A2h + (r0 + 8) * K2P + kg + 8);
            unsigned al0 = ld32(A2l + r0 * K2P + kg);
            unsigned al1 = ld32(A2l + (r0 + 8) * K2P + kg);
            unsigned al2 = ld32(A2l + r0 * K2P + kg + 8);
            unsigned al3 = ld32(A2l + (r0 + 8) * K2P + kg + 8);
#pragma unroll
            for (int j = 0; j < 8; j++) {
                int xc = nw * 64 + j * 8 + qr;
                unsigned bh0 = ld32(Hh + xc * HP + kk);
                unsigned bh1 = ld32(Hh + xc * HP + kk + 8);
                unsigned bl0 = ld32(Hl + xc * HP + kk);
                unsigned bl1 = ld32(Hl + xc * HP + kk + 8);
                mma_bf16(c2[j], ah0, ah1, ah2, ah3, bh0, bh1);
                mma_bf16(c2[j], ah0, ah1, ah2, ah3, bl0, bl1);
                mma_bf16(c2[j], al0, al1, al2, al3, bh0, bh1);
            }
        }
        __syncthreads();
    }

    int e0 = r0, e1 = r0 + 8;
#pragma unroll
    for (int j = 0; j < 8; j++) {
        int xc = nw * 64 + j * 8 + qc * 2;
        if (e0 < COUTC) {
            *(float2*)(out + (bb * COUTC + e0) * NPIX + y * 256 + xc) =
                make_float2(c2[j][0] + b2s[e0], c2[j][1] + b2s[e0]);
        }
        if (e1 < COUTC) {
            *(float2*)(out + (bb * COUTC + e1) * NPIX + y * 256 + xc) =
                make_float2(c2[j][2] + b2s[e1], c2[j][3] + b2s[e1]);
        }
    }
}

// ---------------- launch ------------------------------------------------------
extern "C" void kernel_launch(void* const* d_in, const int* in_sizes, int n_in,
                              void* d_out, int out_size) {
    const float* x    = (const float*)d_in[0];
    const float* w1r  = (const float*)d_in[1];
    const float* w1i  = (const float*)d_in[2];
    const float* w2r  = (const float*)d_in[3];
    const float* w2i  = (const float*)d_in[4];
    const float* pw_w = (const float*)d_in[5];
    const float* pw_b = (const float*)d_in[6];
    const float* fc0w = (const float*)d_in[7];
    const float* fc0b = (const float*)d_in[8];
    const float* fc1w = (const float*)d_in[9];
    const float* fc1b = (const float*)d_in[10];
    const float* fc2w = (const float*)d_in[11];
    const float* fc2b = (const float*)d_in[12];
    float* out = (float*)d_out;

    cudaFuncSetAttribute(k_fuse_mma, cudaFuncAttributeMaxDynamicSharedMemorySize, FUSE2_SMEM);
    cudaFuncSetAttribute(k_fwdX_mma, cudaFuncAttributeMaxDynamicSharedMemorySize, FWDX2_SMEM);
    cudaFuncSetAttribute(k_fwdY_mma, cudaFuncAttributeMaxDynamicSharedMemorySize, FWDY2_SMEM);
    cudaFuncSetAttribute(k_invY_mma, cudaFuncAttributeMaxDynamicSharedMemorySize, INVY2_SMEM);
    cudaFuncSetAttribute(k_head_mma, cudaFuncAttributeMaxDynamicSharedMemorySize, HEAD2_SMEM);

    k_init_basis<<<32, 256>>>();
    k_lift<<<4096, 256>>>(x, fc0w, fc0b);
    for (int l = 0; l < NL; l++) {
        k_fwdX_mma<<<2048, 256, FWDX2_SMEM>>>();
        k_fwdY_mma<<<1024, 256, FWDY2_SMEM>>>();
        k_mix<<<512, 256>>>(w1r, w1i, w2r, w2i, l);
        k_invY_mma<<<1024, 256, INVY2_SMEM>>>();
        k_fuse_mma<<<4096, 256, FUSE2_SMEM>>>(pw_w, pw_b, l, (l < NL - 1) ? 1 : 0);
    }
    k_head_mma<<<4096, 256, HEAD2_SMEM>>>(fc1w, fc1b, fc2w, fc2b, out);
}